// round 8
// baseline (speedup 1.0000x reference)
#include <cuda_runtime.h>
#include <cuda_fp16.h>
#include <cstdint>

#define N_NODES 4096
#define IN_FEAT 512
#define E3      1536
#define HEADS   8
#define HEAD_DIM 64

#define TS_MMA   39          // MMA handles k-tiles [0,39) = keys [0,2496)
#define SC_KEY0  2496        // scalar handles keys [2496,4096) = 50 subtiles of 32
#define SC_NSUB  25          // per pair (even/odd interleave)

// ---------------- scratch (static device globals: no allocation) ------------
__device__ float    g_xT[IN_FEAT * N_NODES];
__device__ float    g_WT[IN_FEAT * E3];
__device__ float    g_Qh[HEADS * N_NODES * 64];  // head-major [h][node][d]
__device__ float    g_Kh[HEADS * N_NODES * 64];
__device__ __half   g_Kp16[HEADS * 64 * 4096];   // fragment-ordered fp16 (MMA)
__device__ __half   g_K16[HEADS * N_NODES * 64]; // plain fp16 rows (scalar)
__device__ float    g_V[N_NODES * 512];
__device__ unsigned g_adjbits[128 * N_NODES];    // [word][q]
__device__ int      g_argmax[HEADS * N_NODES];
__device__ int      g_fixcount;
__device__ int      g_fixlist[HEADS * N_NODES];

// ---------------- packed fp32x2 helpers (qkv gemm) ---------------------------
__device__ __forceinline__ unsigned long long pack2(float lo, float hi) {
    unsigned long long r;
    asm("mov.b64 %0, {%1, %2};" : "=l"(r) : "f"(lo), "f"(hi));
    return r;
}
__device__ __forceinline__ void unpack2(unsigned long long v, float& lo, float& hi) {
    asm("mov.b64 {%0, %1}, %2;" : "=f"(lo), "=f"(hi) : "l"(v));
}
__device__ __forceinline__ unsigned long long fma2(unsigned long long a,
                                                   unsigned long long b,
                                                   unsigned long long c) {
    unsigned long long d;
    asm("fma.rn.f32x2 %0, %1, %2, %3;" : "=l"(d) : "l"(a), "l"(b), "l"(c));
    return d;
}

// ---------------- mbarrier + bulk-copy helpers --------------------------------
__device__ __forceinline__ uint32_t smem_u32(const void* p) {
    uint32_t a;
    asm("{ .reg .u64 t; cvta.to.shared.u64 t, %1; cvt.u32.u64 %0, t; }"
        : "=r"(a) : "l"(p));
    return a;
}
__device__ __forceinline__ void mbar_init(uint32_t bar, uint32_t cnt) {
    asm volatile("mbarrier.init.shared.b64 [%0], %1;" :: "r"(bar), "r"(cnt) : "memory");
}
__device__ __forceinline__ void mbar_arrive_expect(uint32_t bar, uint32_t bytes) {
    asm volatile("mbarrier.arrive.expect_tx.shared.b64 _, [%0], %1;"
                 :: "r"(bar), "r"(bytes) : "memory");
}
__device__ __forceinline__ void bulk_g2s(uint32_t dst, const void* src,
                                         uint32_t bytes, uint32_t bar) {
    asm volatile(
        "cp.async.bulk.shared::cluster.global.mbarrier::complete_tx::bytes "
        "[%0], [%1], %2, [%3];"
        :: "r"(dst), "l"(src), "r"(bytes), "r"(bar) : "memory");
}
__device__ __forceinline__ void mbar_wait(uint32_t bar, uint32_t parity) {
    asm volatile(
        "{\n\t"
        ".reg .pred P;\n\t"
        "WL_%=:\n\t"
        "mbarrier.try_wait.parity.acquire.cta.shared::cta.b64 P, [%0], %1, 0x989680;\n\t"
        "@P bra WD_%=;\n\t"
        "bra WL_%=;\n\t"
        "WD_%=:\n\t"
        "}"
        :: "r"(bar), "r"(parity) : "memory");
}
__device__ __forceinline__ void named_bar(int id, int cnt) {
    asm volatile("bar.sync %0, %1;" :: "r"(id), "r"(cnt) : "memory");
}

// ---------------- fp16 MMA helpers --------------------------------------------
__device__ __forceinline__ uint32_t pack_h2(float x, float y) {
    __half2 v = __floats2half2_rn(x, y);
    return *reinterpret_cast<uint32_t*>(&v);
}
__device__ __forceinline__ void mma16(float* d, const uint32_t* a,
                                      uint32_t b0, uint32_t b1) {
    asm("mma.sync.aligned.m16n8k16.row.col.f32.f16.f16.f32 "
        "{%0,%1,%2,%3}, {%4,%5,%6,%7}, {%8,%9}, {%0,%1,%2,%3};"
        : "+f"(d[0]), "+f"(d[1]), "+f"(d[2]), "+f"(d[3])
        : "r"(a[0]), "r"(a[1]), "r"(a[2]), "r"(a[3]), "r"(b0), "r"(b1));
}

// ============================================================================
// Transposes (unchanged)
// ============================================================================
__global__ __launch_bounds__(256) void transpose_x(const float* __restrict__ x) {
    __shared__ float t[32][33];
    const int bx = blockIdx.x * 32, by = blockIdx.y * 32;
    const int txx = threadIdx.x, tyy = threadIdx.y;
#pragma unroll
    for (int i = tyy; i < 32; i += 8)
        t[i][txx] = x[(size_t)(by + i) * IN_FEAT + bx + txx];
    __syncthreads();
#pragma unroll
    for (int i = tyy; i < 32; i += 8)
        g_xT[(size_t)(bx + i) * N_NODES + by + txx] = t[txx][i];
}

__global__ __launch_bounds__(256) void transpose_w(const float* __restrict__ WQ,
                                                   const float* __restrict__ WK,
                                                   const float* __restrict__ WV) {
    const float* W = (blockIdx.z == 0) ? WQ : ((blockIdx.z == 1) ? WK : WV);
    __shared__ float t[32][33];
    const int bx = blockIdx.x * 32, by = blockIdx.y * 32;
    const int txx = threadIdx.x, tyy = threadIdx.y;
#pragma unroll
    for (int i = tyy; i < 32; i += 8)
        t[i][txx] = W[(size_t)(by + i) * IN_FEAT + bx + txx];
    __syncthreads();
#pragma unroll
    for (int i = tyy; i < 32; i += 8)
        g_WT[(size_t)(bx + i) * E3 + blockIdx.z * 512 + by + txx] = t[txx][i];
}

// ============================================================================
// adj -> bitmask  [word][q]
// ============================================================================
__global__ __launch_bounds__(256) void adj_to_bits(const int* __restrict__ adj) {
    const int q    = blockIdx.x * 8 + (threadIdx.x >> 5);
    const int lane = threadIdx.x & 31;
    const int* row = adj + (size_t)q * N_NODES;
#pragma unroll 4
    for (int w = 0; w < 128; w++) {
        unsigned m = __ballot_sync(0xffffffffu, row[w * 32 + lane] > 0);
        if (lane == 0) g_adjbits[w * N_NODES + q] = m;
    }
}

// ============================================================================
// QKV GEMM (fp32-exact, at its f32x2 floor) — unchanged
// ============================================================================
#define QKV_KT 64
#define QKV_SMEM (4 * QKV_KT * 128 * 4)

__device__ __forceinline__ void qkv_issue(int t, int m0, int n0, int tid,
                                          float* As, float* Bs,
                                          uint32_t bar0, uint32_t bar1) {
    if (tid < 128) {
        const int buf = t & 1;
        const uint32_t bar = buf ? bar1 : bar0;
        mbar_arrive_expect(bar, 512);
        const int row = tid & 63;
        const int k   = t * QKV_KT + row;
        if (tid < 64) {
            bulk_g2s(smem_u32(&As[buf * QKV_KT * 128 + row * 128]),
                     &g_xT[(size_t)k * N_NODES + m0], 512, bar);
        } else {
            bulk_g2s(smem_u32(&Bs[buf * QKV_KT * 128 + row * 128]),
                     &g_WT[(size_t)k * E3 + n0], 512, bar);
        }
    }
}

__global__ __launch_bounds__(512, 1) void qkv_gemm() {
    extern __shared__ float smem[];
    float* As = smem;
    float* Bs = smem + 2 * QKV_KT * 128;
    __shared__ __align__(8) unsigned long long mbar[2];

    const int tid = threadIdx.x;
    const int tx  = tid & 31;
    const int ty  = tid >> 5;
    const int n0  = blockIdx.x * 128;
    const int m0  = blockIdx.y * 128;
    const uint32_t bar0 = smem_u32(&mbar[0]);
    const uint32_t bar1 = smem_u32(&mbar[1]);

    if (blockIdx.x == 0 && blockIdx.y == 0 && tid == 0) g_fixcount = 0;

    if (tid == 0) { mbar_init(bar0, 128); mbar_init(bar1, 128); }
    __syncthreads();

    qkv_issue(0, m0, n0, tid, As, Bs, bar0, bar1);
    qkv_issue(1, m0, n0, tid, As, Bs, bar0, bar1);

    unsigned long long c[4][4];
#pragma unroll
    for (int i = 0; i < 4; i++)
#pragma unroll
        for (int j = 0; j < 4; j++) c[i][j] = 0ULL;

    const int ntiles = IN_FEAT / QKV_KT;
    for (int t = 0; t < ntiles; t++) {
        const int buf = t & 1;
        mbar_wait(buf ? bar1 : bar0, (t >> 1) & 1);
        const float* a = As + buf * QKV_KT * 128;
        const float* b = Bs + buf * QKV_KT * 128;
#pragma unroll 8
        for (int k = 0; k < QKV_KT; k++) {
            const ulonglong2* ap = (const ulonglong2*)&a[k * 128 + ty * 8];
            ulonglong2 a01 = ap[0];
            ulonglong2 a23 = ap[1];
            float4 bv = *(const float4*)&b[k * 128 + tx * 4];
            unsigned long long bd[4];
            bd[0] = pack2(bv.x, bv.x);
            bd[1] = pack2(bv.y, bv.y);
            bd[2] = pack2(bv.z, bv.z);
            bd[3] = pack2(bv.w, bv.w);
#pragma unroll
            for (int j = 0; j < 4; j++) {
                c[0][j] = fma2(a01.x, bd[j], c[0][j]);
                c[1][j] = fma2(a01.y, bd[j], c[1][j]);
                c[2][j] = fma2(a23.x, bd[j], c[2][j]);
                c[3][j] = fma2(a23.y, bd[j], c[3][j]);
            }
        }
        __syncthreads();
        if (t + 2 < ntiles) qkv_issue(t + 2, m0, n0, tid, As, Bs, bar0, bar1);
    }

    const int col = (n0 & 511) + tx * 4;
    float* pb;
    size_t rs;
    if (n0 < 512)       { pb = g_Qh + (size_t)(col >> 6) * (N_NODES * 64) + (col & 63); rs = 64; }
    else if (n0 < 1024) { pb = g_Kh + (size_t)(col >> 6) * (N_NODES * 64) + (col & 63); rs = 64; }
    else                { pb = g_V + col; rs = 512; }

#pragma unroll
    for (int mp = 0; mp < 4; mp++) {
        float lo0, hi0, lo1, hi1, lo2, hi2, lo3, hi3;
        unpack2(c[mp][0], lo0, hi0);
        unpack2(c[mp][1], lo1, hi1);
        unpack2(c[mp][2], lo2, hi2);
        unpack2(c[mp][3], lo3, hi3);
        const size_t row0 = m0 + ty * 8 + mp * 2;
        *(float4*)&pb[row0 * rs]       = make_float4(lo0, lo1, lo2, lo3);
        *(float4*)&pb[(row0 + 1) * rs] = make_float4(hi0, hi1, hi2, hi3);
    }
}

// ============================================================================
// K -> fp16: (a) fragment-ordered images for MMA; (b) plain rows for scalar.
// ============================================================================
__global__ __launch_bounds__(256) void convert_k16() {
    const int t = blockIdx.x, h = blockIdx.y;
    const float* src = g_Kh + ((size_t)h * N_NODES + t * 64) * 64;
    __half2* dst = (__half2*)(g_Kp16 + ((size_t)(h * 64 + t)) * 4096);
#pragma unroll
    for (int it = 0; it < 4; it++) {
        const int id   = it * 256 + threadIdx.x;
        const int lane = id & 31;
        const int s    = (id >> 5) & 3;
        const int nf   = id >> 7;
        const int key  = nf * 8 + (lane >> 2);
        const int kc   = s * 16 + (lane & 3) * 2;
        const float* p = src + key * 64 + kc;
        dst[id * 2]     = __floats2half2_rn(p[0], p[1]);
        dst[id * 2 + 1] = __floats2half2_rn(p[8], p[9]);
    }
    // plain copy: 2048 half2 per (t,h)
    __half2* pd = (__half2*)(g_K16 + ((size_t)h * N_NODES + t * 64) * 64);
#pragma unroll
    for (int it = 0; it < 8; it++) {
        const int id = it * 256 + threadIdx.x;     // 0..2047
        pd[id] = __floats2half2_rn(src[id * 2], src[id * 2 + 1]);
    }
}

// ============================================================================
// rare index recovery for the MMA path (from R7)
// ============================================================================
__device__ __forceinline__ void rare2(const float (&acc)[8][4], int cofs,
                                      int t, int l4, float tmax,
                                      float& best, float& best2, int& bk) {
    float sec = -3e38f;
    int   idx = bk;
    bool  taken = false;
#pragma unroll
    for (int nf = 0; nf < 8; nf++)
#pragma unroll
        for (int c = 0; c < 2; c++) {
            const float v = acc[nf][cofs + c];
            if (v == tmax && !taken) {
                taken = true;
                idx = t * 64 + nf * 8 + l4 * 2 + c;
            } else {
                sec = fmaxf(sec, v);
            }
        }
    best2 = fmaxf(best2, fmaxf(best, sec));
    best  = tmax;
    bk    = idx;
}

// ============================================================================
// HYBRID score kernel: warps 0-3 fp16 MMA on keys [0,2496);
// warps 4-7 HFMA2 scalar on keys [2496,4096). Block = (64 q, head).
// ============================================================================
__global__ __launch_bounds__(256, 2) void score_hybrid() {
    __shared__ __align__(16) __half sKm[3][4096];       // MMA ring, 3 x 8 KB
    __shared__ __align__(16) __half sKs[2][2][2048];    // scalar pair rings, 4 x 4 KB
    __shared__ __align__(8) unsigned long long s_barM[3], s_barS[2][2];
    __shared__ float mB[3][64], mB2[3][64];
    __shared__ int   mI[3][64];

    const int tid  = threadIdx.x;
    const int wid  = tid >> 5;
    const int lane = tid & 31;
    const int h    = blockIdx.y;
    const int qt   = blockIdx.x;

    if (tid == 0) {
#pragma unroll
        for (int i = 0; i < 3; i++) mbar_init(smem_u32(&s_barM[i]), 1);
#pragma unroll
        for (int p = 0; p < 2; p++)
#pragma unroll
            for (int i = 0; i < 2; i++) mbar_init(smem_u32(&s_barS[p][i]), 1);
    }
    __syncthreads();

    if (wid < 4) {
        // =========================== MMA half ===========================
        const int g  = lane >> 2;
        const int l4 = lane & 3;
        const int qA = qt * 64 + wid * 16 + g;
        const int qB = qA + 8;
        const __half* Ksrc = g_Kp16 + (size_t)h * 64 * 4096;

        if (tid == 0) {
#pragma unroll
            for (int i = 0; i < 3; i++) {
                mbar_arrive_expect(smem_u32(&s_barM[i]), 8192);
                bulk_g2s(smem_u32(&sKm[i][0]), Ksrc + (size_t)i * 4096, 8192,
                         smem_u32(&s_barM[i]));
            }
        }

        uint32_t a[4][4];
        {
            const float* QA = g_Qh + ((size_t)h * N_NODES + qA) * 64;
            const float* QB = QA + 8 * 64;
#pragma unroll
            for (int s = 0; s < 4; s++) {
                const int c = s * 16 + 2 * l4;
                a[s][0] = pack_h2(QA[c],     QA[c + 1]);
                a[s][1] = pack_h2(QB[c],     QB[c + 1]);
                a[s][2] = pack_h2(QA[c + 8], QA[c + 9]);
                a[s][3] = pack_h2(QB[c + 8], QB[c + 9]);
            }
        }

        float bestA = -3.3e38f, best2A = -3.3e38f;
        float bestB = -3.3e38f, best2B = -3.3e38f;
        int   bkA = 0, bkB = 0;
        int   phM[3] = {0, 0, 0};

        for (int t = 0; t < TS_MMA; t++) {
            const int buf = t % 3;
            mbar_wait(smem_u32(&s_barM[buf]), phM[buf]);
            phM[buf] ^= 1;

            const unsigned w0A = g_adjbits[(size_t)(2 * t)     * N_NODES + qA];
            const unsigned w1A = g_adjbits[(size_t)(2 * t + 1) * N_NODES + qA];
            const unsigned w0B = g_adjbits[(size_t)(2 * t)     * N_NODES + qB];
            const unsigned w1B = g_adjbits[(size_t)(2 * t + 1) * N_NODES + qB];

            float acc[8][4];
#pragma unroll
            for (int nf = 0; nf < 8; nf++) {
                const unsigned wdA = (nf < 4) ? w0A : w1A;
                const unsigned wdB = (nf < 4) ? w0B : w1B;
                const int sh = (nf & 3) * 8 + l4 * 2;
                acc[nf][0] = ((wdA >> sh) & 1u)       ? 0.0f : -3e38f;
                acc[nf][1] = ((wdA >> (sh + 1)) & 1u) ? 0.0f : -3e38f;
                acc[nf][2] = ((wdB >> sh) & 1u)       ? 0.0f : -3e38f;
                acc[nf][3] = ((wdB >> (sh + 1)) & 1u) ? 0.0f : -3e38f;
            }

            const __half* kb = &sKm[buf][0];
#pragma unroll
            for (int nf = 0; nf < 8; nf++) {
#pragma unroll
                for (int s = 0; s < 4; s++) {
                    const uint2 bb = *(const uint2*)&kb[(size_t)(((nf * 4 + s) * 32 + lane)) * 4];
                    mma16(acc[nf], a[s], bb.x, bb.y);
                }
            }
            named_bar(1, 128);
            if (tid == 0 && t + 3 < TS_MMA) {
                mbar_arrive_expect(smem_u32(&s_barM[buf]), 8192);
                bulk_g2s(smem_u32(&sKm[buf][0]),
                         Ksrc + (size_t)(t + 3) * 4096, 8192,
                         smem_u32(&s_barM[buf]));
            }

            float tA = fmaxf(acc[0][0], acc[0][1]);
            float tB = fmaxf(acc[0][2], acc[0][3]);
#pragma unroll
            for (int nf = 1; nf < 8; nf++) {
                tA = fmaxf(tA, fmaxf(acc[nf][0], acc[nf][1]));
                tB = fmaxf(tB, fmaxf(acc[nf][2], acc[nf][3]));
            }
            if (tA > bestA) rare2(acc, 0, t, l4, tA, bestA, best2A, bkA);
            else            best2A = fmaxf(best2A, tA);
            if (tB > bestB) rare2(acc, 2, t, l4, tB, bestB, best2B, bkB);
            else            best2B = fmaxf(best2B, tB);
        }

#pragma unroll
        for (int off = 1; off < 4; off <<= 1) {
            float ob  = __shfl_xor_sync(0xffffffffu, bestA, off);
            int   obk = __shfl_xor_sync(0xffffffffu, bkA,  off);
            float ob2 = __shfl_xor_sync(0xffffffffu, best2A, off);
            best2A = fmaxf(fmaxf(best2A, ob2), fminf(bestA, ob));
            if (ob > bestA || (ob == bestA && obk < bkA)) { bestA = ob; bkA = obk; }

            ob  = __shfl_xor_sync(0xffffffffu, bestB, off);
            obk = __shfl_xor_sync(0xffffffffu, bkB,  off);
            ob2 = __shfl_xor_sync(0xffffffffu, best2B, off);
            best2B = fmaxf(fmaxf(best2B, ob2), fminf(bestB, ob));
            if (ob > bestB || (ob == bestB && obk < bkB)) { bestB = ob; bkB = obk; }
        }
        if (l4 == 0) {
            const int qa = wid * 16 + g;
            mB[0][qa] = bestA;  mB2[0][qa] = best2A;  mI[0][qa] = bkA;
            mB[0][qa + 8] = bestB; mB2[0][qa + 8] = best2B; mI[0][qa + 8] = bkB;
        }
    } else {
        // ========================= scalar half (HFMA2) =========================
        const int pair = (wid >= 6) ? 1 : 0;
        const int qloc = ((wid & 1) ? 32 : 0) + lane;
        const int q    = qt * 64 + qloc;
        const bool producer = (lane == 0) && ((wid == 4) || (wid == 6));
        const __half* Ksrc = g_K16 + ((size_t)h * N_NODES + SC_KEY0) * 64;

        if (producer) {
#pragma unroll
            for (int i = 0; i < 2; i++) {
                const int st = 2 * i + pair;
                mbar_arrive_expect(smem_u32(&s_barS[pair][i]), 4096);
                bulk_g2s(smem_u32(&sKs[pair][i][0]),
                         Ksrc + (size_t)st * 32 * 64, 4096,
                         smem_u32(&s_barS[pair][i]));
            }
        }

        // Q row -> 32 half2
        __half2 qh[32];
        {
            const float* Qr = g_Qh + ((size_t)h * N_NODES + q) * 64;
#pragma unroll
            for (int j = 0; j < 32; j++)
                qh[j] = __floats2half2_rn(Qr[2 * j], Qr[2 * j + 1]);
        }

        float best = -3.3e38f, best2 = -3.3e38f;
        int   bk = 0;
        int   phS[2] = {0, 0};

        for (int i = 0; i < SC_NSUB; i++) {
            const int buf = i & 1;
            mbar_wait(smem_u32(&s_barS[pair][buf]), phS[buf]);
            phS[buf] ^= 1;

            const int st = 2 * i + pair;
            const int k0 = SC_KEY0 + st * 32;
            const unsigned word = g_adjbits[(size_t)(k0 >> 5) * N_NODES + q];
            const __half* kb = &sKs[pair][buf][0];

#pragma unroll 2
            for (int kk = 0; kk < 32; kk++) {
                uint4 kv[4];
                const uint4* kp = (const uint4*)&kb[kk * 64];
                kv[0] = kp[0]; kv[1] = kp[1]; kv[2] = kp[2]; kv[3] = kp[3];
                uint4 kv2[4];
                kv2[0] = kp[4]; kv2[1] = kp[5]; kv2[2] = kp[6]; kv2[3] = kp[7];
                const __half2* k1 = reinterpret_cast<const __half2*>(kv);
                const __half2* k2 = reinterpret_cast<const __half2*>(kv2);

                __half2 acc[8];
#pragma unroll
                for (int j = 0; j < 8; j++)
                    acc[j] = __hmul2(qh[j], k1[j]);
#pragma unroll
                for (int j = 8; j < 16; j++)
                    acc[j - 8] = __hfma2(qh[j], k1[j], acc[j - 8]);
#pragma unroll
                for (int j = 0; j < 8; j++)
                    acc[j] = __hfma2(qh[16 + j], k2[j], acc[j]);
#pragma unroll
                for (int j = 8; j < 16; j++)
                    acc[j - 8] = __hfma2(qh[16 + j], k2[j], acc[j - 8]);

                __half2 t0 = __hadd2(acc[0], acc[1]);
                __half2 t1 = __hadd2(acc[2], acc[3]);
                __half2 t2 = __hadd2(acc[4], acc[5]);
                __half2 t3 = __hadd2(acc[6], acc[7]);
                t0 = __hadd2(t0, t1);
                t2 = __hadd2(t2, t3);
                float2 f0 = __half22float2(t0);
                float2 f1 = __half22float2(t2);
                const float s = (f0.x + f0.y) + (f1.x + f1.y);

                if ((word >> kk) & 1u) {
                    if (s > best) { best2 = best; best = s; bk = k0 + kk; }
                    else          best2 = fmaxf(best2, s);
                }
            }
            named_bar(2 + pair, 64);
            if (producer && i + 2 < SC_NSUB) {
                const int st2 = 2 * (i + 2) + pair;
                mbar_arrive_expect(smem_u32(&s_barS[pair][buf]), 4096);
                bulk_g2s(smem_u32(&sKs[pair][buf][0]),
                         Ksrc + (size_t)st2 * 32 * 64, 4096,
                         smem_u32(&s_barS[pair][buf]));
            }
        }

        mB[1 + pair][qloc] = best;
        mB2[1 + pair][qloc] = best2;
        mI[1 + pair][qloc] = bk;
    }

    __syncthreads();

    // ---------------- merge 3 sources per q, error-aware band ----------------
    if (tid < 64) {
        const float err[3] = {0.0375f, 0.09f, 0.09f};
        float b0 = mB[0][tid], b1 = mB[1][tid], b2 = mB[2][tid];
        int wsrc = 0;
        float best = b0;
        if (b1 > best) { best = b1; wsrc = 1; }
        if (b2 > best) { best = b2; wsrc = 2; }
        const int idx = mI[wsrc][tid];

        bool flag = false;
#pragma unroll
        for (int s = 0; s < 3; s++) {
            const float gap = (s == wsrc) ? (best - mB2[s][tid])
                                          : (best - mB[s][tid]);
            const float thr = err[wsrc] + err[s];
            flag |= (gap < thr);
        }

        const int hq = h * N_NODES + qt * 64 + tid;
        g_argmax[hq] = idx;
        if (flag) g_fixlist[atomicAdd(&g_fixcount, 1)] = hq;
    }
}

// ============================================================================
// Pass 2: exact fp32 re-argmax of flagged rows (block per row).
// ============================================================================
__global__ __launch_bounds__(256) void rescan() {
    __shared__ float s_best[8];
    __shared__ int   s_bk[8];
    const int nfix = g_fixcount;
    const int tid = threadIdx.x, lane = tid & 31, wrp = tid >> 5;

    for (int i = blockIdx.x; i < nfix; i += gridDim.x) {
        const int hq = g_fixlist[i];
        const int h = hq >> 12, q = hq & (N_NODES - 1);
        const float* Qr = g_Qh + ((size_t)h * N_NODES + q) * 64;
        float qv[64];
#pragma unroll
        for (int j = 0; j < 16; j++) {
            float4 v = *(const float4*)&Qr[j * 4];
            qv[j*4] = v.x; qv[j*4+1] = v.y; qv[j*4+2] = v.z; qv[j*4+3] = v.w;
        }

        float best = -3e38f;
        int   bk   = 1 << 30;
        for (int k = tid; k < N_NODES; k += 256) {
            const unsigned wd = g_adjbits[(k >> 5) * N_NODES + q];
            if ((wd >> (k & 31)) & 1u) {
                const float* Kr = g_Kh + ((size_t)h * N_NODES + k) * 64;
                float d = 0.f;
#pragma unroll
                for (int j = 0; j < 16; j++) {
                    float4 v = *(const float4*)&Kr[j * 4];
                    d += qv[j*4] * v.x + qv[j*4+1] * v.y
                       + qv[j*4+2] * v.z + qv[j*4+3] * v.w;
                }
                if (d > best || (d == best && k < bk)) { best = d; bk = k; }
            }
        }
#pragma unroll
        for (int off = 16; off > 0; off >>= 1) {
            float ob  = __shfl_xor_sync(0xffffffffu, best, off);
            int   obk = __shfl_xor_sync(0xffffffffu, bk, off);
            if (ob > best || (ob == best && obk < bk)) { best = ob; bk = obk; }
        }
        if (lane == 0) { s_best[wrp] = best; s_bk[wrp] = bk; }
        __syncthreads();
        if (tid == 0) {
            float b = s_best[0]; int k = s_bk[0];
#pragma unroll
            for (int j = 1; j < 8; j++)
                if (s_best[j] > b || (s_best[j] == b && s_bk[j] < k)) {
                    b = s_best[j]; k = s_bk[j];
                }
            g_argmax[hq] = k;
        }
        __syncthreads();
    }
}

// ============================================================================
// out[q, h*64+d] = V[argmax(h,q), h*64+d] / HEADS
// ============================================================================
__global__ __launch_bounds__(256) void gather_out(float* __restrict__ out) {
    const int idx = blockIdx.x * blockDim.x + threadIdx.x;
    const int q   = idx >> 7;
    const int c4  = idx & 127;
    const int h   = c4 >> 4;
    const int k   = g_argmax[h * N_NODES + q];
    float4 t = *(const float4*)&g_V[(size_t)k * 512 + c4 * 4];
    float4 v = make_float4(t.x * 0.125f, t.y * 0.125f, t.z * 0.125f, t.w * 0.125f);
    *(float4*)&out[(size_t)idx * 4] = v;
}

// ============================================================================
extern "C" void kernel_launch(void* const* d_in, const int* in_sizes, int n_in,
                              void* d_out, int out_size)
{
    const float* x   = (const float*)d_in[0];
    const int*   adj = (const int*)d_in[1];
    const float* WQ  = (const float*)d_in[2];
    const float* WK  = (const float*)d_in[3];
    const float* WV  = (const float*)d_in[4];
    float* out = (float*)d_out;

    cudaFuncSetAttribute(qkv_gemm,
                         cudaFuncAttributeMaxDynamicSharedMemorySize, QKV_SMEM);

    dim3 tb(32, 8);
    transpose_x<<<dim3(IN_FEAT / 32, N_NODES / 32), tb>>>(x);
    transpose_w<<<dim3(IN_FEAT / 32, 512 / 32, 3), tb>>>(WQ, WK, WV);
    adj_to_bits<<<N_NODES / 8, 256>>>(adj);

    qkv_gemm<<<dim3(E3 / 128, N_NODES / 128), 512, QKV_SMEM>>>();

    convert_k16<<<dim3(64, HEADS), 256>>>();

    score_hybrid<<<dim3(N_NODES / 64, HEADS), 256>>>();

    rescan<<<2048, 256>>>();

    gather_out<<<(N_NODES * 512 / 4) / 256, 256>>>(out);
}

// round 9
// speedup vs baseline: 1.5955x; 1.5955x over previous
#include <cuda_runtime.h>
#include <cuda_fp16.h>
#include <cstdint>

#define N_NODES 4096
#define IN_FEAT 512
#define E3      1536
#define HEADS   8
#define HEAD_DIM 64
#define BAND    0.075f

// ---------------- scratch (static device globals: no allocation) ------------
__device__ float    g_xT[IN_FEAT * N_NODES];     // [k][m]
__device__ float    g_WT[IN_FEAT * E3];          // [k][n]
__device__ float    g_Qh[HEADS * N_NODES * 64];  // head-major [h][node][d]
__device__ float    g_Kh[HEADS * N_NODES * 64];
__device__ __half   g_Kp16[HEADS * 64 * 4096];   // fragment-PAIRED fp16 tile images
__device__ float    g_V[N_NODES * 512];          // node-major
__device__ unsigned g_adjbits[128 * N_NODES];    // [word][q]
__device__ int      g_argmax[HEADS * N_NODES];
__device__ int      g_fixcount;
__device__ int      g_fixlist[HEADS * N_NODES];

// ---------------- packed fp32x2 helpers (qkv gemm) ---------------------------
__device__ __forceinline__ unsigned long long pack2(float lo, float hi) {
    unsigned long long r;
    asm("mov.b64 %0, {%1, %2};" : "=l"(r) : "f"(lo), "f"(hi));
    return r;
}
__device__ __forceinline__ void unpack2(unsigned long long v, float& lo, float& hi) {
    asm("mov.b64 {%0, %1}, %2;" : "=f"(lo), "=f"(hi) : "l"(v));
}
__device__ __forceinline__ unsigned long long fma2(unsigned long long a,
                                                   unsigned long long b,
                                                   unsigned long long c) {
    unsigned long long d;
    asm("fma.rn.f32x2 %0, %1, %2, %3;" : "=l"(d) : "l"(a), "l"(b), "l"(c));
    return d;
}

// ---------------- mbarrier + bulk-copy helpers --------------------------------
__device__ __forceinline__ uint32_t smem_u32(const void* p) {
    uint32_t a;
    asm("{ .reg .u64 t; cvta.to.shared.u64 t, %1; cvt.u32.u64 %0, t; }"
        : "=r"(a) : "l"(p));
    return a;
}
__device__ __forceinline__ void mbar_init(uint32_t bar, uint32_t cnt) {
    asm volatile("mbarrier.init.shared.b64 [%0], %1;" :: "r"(bar), "r"(cnt) : "memory");
}
__device__ __forceinline__ void mbar_arrive_expect(uint32_t bar, uint32_t bytes) {
    asm volatile("mbarrier.arrive.expect_tx.shared.b64 _, [%0], %1;"
                 :: "r"(bar), "r"(bytes) : "memory");
}
__device__ __forceinline__ void bulk_g2s(uint32_t dst, const void* src,
                                         uint32_t bytes, uint32_t bar) {
    asm volatile(
        "cp.async.bulk.shared::cluster.global.mbarrier::complete_tx::bytes "
        "[%0], [%1], %2, [%3];"
        :: "r"(dst), "l"(src), "r"(bytes), "r"(bar) : "memory");
}
__device__ __forceinline__ void mbar_wait(uint32_t bar, uint32_t parity) {
    asm volatile(
        "{\n\t"
        ".reg .pred P;\n\t"
        "WL_%=:\n\t"
        "mbarrier.try_wait.parity.acquire.cta.shared::cta.b64 P, [%0], %1, 0x989680;\n\t"
        "@P bra WD_%=;\n\t"
        "bra WL_%=;\n\t"
        "WD_%=:\n\t"
        "}"
        :: "r"(bar), "r"(parity) : "memory");
}

// ---------------- fp16 MMA helpers --------------------------------------------
__device__ __forceinline__ uint32_t pack_h2(float x, float y) {
    __half2 v = __floats2half2_rn(x, y);
    return *reinterpret_cast<uint32_t*>(&v);
}
__device__ __forceinline__ void mma16(float* d, const uint32_t* a,
                                      uint32_t b0, uint32_t b1) {
    asm("mma.sync.aligned.m16n8k16.row.col.f32.f16.f16.f32 "
        "{%0,%1,%2,%3}, {%4,%5,%6,%7}, {%8,%9}, {%0,%1,%2,%3};"
        : "+f"(d[0]), "+f"(d[1]), "+f"(d[2]), "+f"(d[3])
        : "r"(a[0]), "r"(a[1]), "r"(a[2]), "r"(a[3]), "r"(b0), "r"(b1));
}

// ============================================================================
// Merged transposes: y<128 -> x-tile; y>=128 -> W-tile.
// ============================================================================
__global__ __launch_bounds__(256) void transpose_xw(const float* __restrict__ x,
                                                    const float* __restrict__ WQ,
                                                    const float* __restrict__ WK,
                                                    const float* __restrict__ WV) {
    __shared__ float t[32][33];
    const int bx = blockIdx.x * 32;
    const int txx = threadIdx.x, tyy = threadIdx.y;

    if (blockIdx.y < 128) {
        const int by = blockIdx.y * 32;
#pragma unroll
        for (int i = tyy; i < 32; i += 8)
            t[i][txx] = x[(size_t)(by + i) * IN_FEAT + bx + txx];
        __syncthreads();
#pragma unroll
        for (int i = tyy; i < 32; i += 8)
            g_xT[(size_t)(bx + i) * N_NODES + by + txx] = t[txx][i];
    } else {
        const int yy = blockIdx.y - 128;
        const int wsel = yy >> 4;                 // 0..2
        const int by = (yy & 15) * 32;
        const float* W = (wsel == 0) ? WQ : ((wsel == 1) ? WK : WV);
#pragma unroll
        for (int i = tyy; i < 32; i += 8)
            t[i][txx] = W[(size_t)(by + i) * IN_FEAT + bx + txx];
        __syncthreads();
#pragma unroll
        for (int i = tyy; i < 32; i += 8)
            g_WT[(size_t)(bx + i) * E3 + wsel * 512 + by + txx] = t[txx][i];
    }
}

// ============================================================================
// adj -> bitmask  [word][q]
// ============================================================================
__global__ __launch_bounds__(256) void adj_to_bits(const int* __restrict__ adj) {
    const int q    = blockIdx.x * 8 + (threadIdx.x >> 5);
    const int lane = threadIdx.x & 31;
    const int* row = adj + (size_t)q * N_NODES;
#pragma unroll 4
    for (int w = 0; w < 128; w++) {
        unsigned m = __ballot_sync(0xffffffffu, row[w * 32 + lane] > 0);
        if (lane == 0) g_adjbits[w * N_NODES + q] = m;
    }
}

// ============================================================================
// QKV GEMM (fp32-exact, at its f32x2 floor) — unchanged
// ============================================================================
#define QKV_KT 64
#define QKV_SMEM (4 * QKV_KT * 128 * 4)

__device__ __forceinline__ void qkv_issue(int t, int m0, int n0, int tid,
                                          float* As, float* Bs,
                                          uint32_t bar0, uint32_t bar1) {
    if (tid < 128) {
        const int buf = t & 1;
        const uint32_t bar = buf ? bar1 : bar0;
        mbar_arrive_expect(bar, 512);
        const int row = tid & 63;
        const int k   = t * QKV_KT + row;
        if (tid < 64) {
            bulk_g2s(smem_u32(&As[buf * QKV_KT * 128 + row * 128]),
                     &g_xT[(size_t)k * N_NODES + m0], 512, bar);
        } else {
            bulk_g2s(smem_u32(&Bs[buf * QKV_KT * 128 + row * 128]),
                     &g_WT[(size_t)k * E3 + n0], 512, bar);
        }
    }
}

__global__ __launch_bounds__(512, 1) void qkv_gemm() {
    extern __shared__ float smem[];
    float* As = smem;
    float* Bs = smem + 2 * QKV_KT * 128;
    __shared__ __align__(8) unsigned long long mbar[2];

    const int tid = threadIdx.x;
    const int tx  = tid & 31;
    const int ty  = tid >> 5;
    const int n0  = blockIdx.x * 128;
    const int m0  = blockIdx.y * 128;
    const uint32_t bar0 = smem_u32(&mbar[0]);
    const uint32_t bar1 = smem_u32(&mbar[1]);

    if (blockIdx.x == 0 && blockIdx.y == 0 && tid == 0) g_fixcount = 0;

    if (tid == 0) { mbar_init(bar0, 128); mbar_init(bar1, 128); }
    __syncthreads();

    qkv_issue(0, m0, n0, tid, As, Bs, bar0, bar1);
    qkv_issue(1, m0, n0, tid, As, Bs, bar0, bar1);

    unsigned long long c[4][4];
#pragma unroll
    for (int i = 0; i < 4; i++)
#pragma unroll
        for (int j = 0; j < 4; j++) c[i][j] = 0ULL;

    const int ntiles = IN_FEAT / QKV_KT;
    for (int t = 0; t < ntiles; t++) {
        const int buf = t & 1;
        mbar_wait(buf ? bar1 : bar0, (t >> 1) & 1);
        const float* a = As + buf * QKV_KT * 128;
        const float* b = Bs + buf * QKV_KT * 128;
#pragma unroll 8
        for (int k = 0; k < QKV_KT; k++) {
            const ulonglong2* ap = (const ulonglong2*)&a[k * 128 + ty * 8];
            ulonglong2 a01 = ap[0];
            ulonglong2 a23 = ap[1];
            float4 bv = *(const float4*)&b[k * 128 + tx * 4];
            unsigned long long bd[4];
            bd[0] = pack2(bv.x, bv.x);
            bd[1] = pack2(bv.y, bv.y);
            bd[2] = pack2(bv.z, bv.z);
            bd[3] = pack2(bv.w, bv.w);
#pragma unroll
            for (int j = 0; j < 4; j++) {
                c[0][j] = fma2(a01.x, bd[j], c[0][j]);
                c[1][j] = fma2(a01.y, bd[j], c[1][j]);
                c[2][j] = fma2(a23.x, bd[j], c[2][j]);
                c[3][j] = fma2(a23.y, bd[j], c[3][j]);
            }
        }
        __syncthreads();
        if (t + 2 < ntiles) qkv_issue(t + 2, m0, n0, tid, As, Bs, bar0, bar1);
    }

    const int col = (n0 & 511) + tx * 4;
    float* pb;
    size_t rs;
    if (n0 < 512)       { pb = g_Qh + (size_t)(col >> 6) * (N_NODES * 64) + (col & 63); rs = 64; }
    else if (n0 < 1024) { pb = g_Kh + (size_t)(col >> 6) * (N_NODES * 64) + (col & 63); rs = 64; }
    else                { pb = g_V + col; rs = 512; }

#pragma unroll
    for (int mp = 0; mp < 4; mp++) {
        float lo0, hi0, lo1, hi1, lo2, hi2, lo3, hi3;
        unpack2(c[mp][0], lo0, hi0);
        unpack2(c[mp][1], lo1, hi1);
        unpack2(c[mp][2], lo2, hi2);
        unpack2(c[mp][3], lo3, hi3);
        const size_t row0 = m0 + ty * 8 + mp * 2;
        *(float4*)&pb[row0 * rs]       = make_float4(lo0, lo1, lo2, lo3);
        *(float4*)&pb[(row0 + 1) * rs] = make_float4(hi0, hi1, hi2, hi3);
    }
}

// ============================================================================
// K -> fp16 fragment-PAIRED tile images (8 KB per 64x64 tile).
// Item id = (nf*2+sp)*32 + lane holds ONE uint4 = both k-step fragments
// (s = 2sp, 2sp+1) for mma(nf, s): key = nf*8 + (lane>>2),
// k0 = sp*32 + (lane&3)*2 -> halves {k0,k0+1},{k0+8,k0+9},{k0+16,k0+17},{k0+24,k0+25}.
// ============================================================================
__global__ __launch_bounds__(256) void convert_k16() {
    const int t = blockIdx.x, h = blockIdx.y;
    const float* src = g_Kh + ((size_t)h * N_NODES + t * 64) * 64;
    __half2* dst = (__half2*)(g_Kp16 + ((size_t)(h * 64 + t)) * 4096);
#pragma unroll
    for (int it = 0; it < 2; it++) {
        const int id   = it * 256 + threadIdx.x;  // 0..511
        const int lane = id & 31;
        const int sp   = (id >> 5) & 1;
        const int nf   = id >> 6;
        const int key  = nf * 8 + (lane >> 2);
        const int k0   = sp * 32 + (lane & 3) * 2;
        const float* p = src + key * 64 + k0;
        dst[id * 4 + 0] = __floats2half2_rn(p[0],  p[1]);
        dst[id * 4 + 1] = __floats2half2_rn(p[8],  p[9]);
        dst[id * 4 + 2] = __floats2half2_rn(p[16], p[17]);
        dst[id * 4 + 3] = __floats2half2_rn(p[24], p[25]);
    }
}

// ============================================================================
// rare index recovery (R7, validated)
// ============================================================================
__device__ __forceinline__ void rare2(const float (&acc)[8][4], int cofs,
                                      int t, int l4, float tmax,
                                      float& best, float& best2, int& bk) {
    float sec = -3e38f;
    int   idx = bk;
    bool  taken = false;
#pragma unroll
    for (int nf = 0; nf < 8; nf++)
#pragma unroll
        for (int c = 0; c < 2; c++) {
            const float v = acc[nf][cofs + c];
            if (v == tmax && !taken) {
                taken = true;
                idx = t * 64 + nf * 8 + l4 * 2 + c;
            } else {
                sec = fmaxf(sec, v);
            }
        }
    best2 = fmaxf(best2, fmaxf(best, sec));
    best  = tmax;
    bk    = idx;
}

// ============================================================================
// Score argmax via mma.sync m16n8k16.f16; mask folded into accumulator init;
// 4-deep bulk-copy ring; paired-fragment LDS.128 B loads.
// Block = 64 q x 1 head, 4 warps.
// ============================================================================
__global__ __launch_bounds__(128, 4) void score_mma() {
    __shared__ __align__(16) __half sK[4][4096];  // 4 x 8 KB ring
    __shared__ __align__(8) unsigned long long s_bar[4];

    const int tid  = threadIdx.x;
    const int w    = tid >> 5;
    const int lane = tid & 31;
    const int g    = lane >> 2;
    const int l4   = lane & 3;
    const int h    = blockIdx.y;
    const int qt   = blockIdx.x;
    const int qA   = qt * 64 + w * 16 + g;
    const int qB   = qA + 8;

    uint32_t bar[4];
#pragma unroll
    for (int i = 0; i < 4; i++) bar[i] = smem_u32(&s_bar[i]);
    const __half* Ksrc = g_Kp16 + (size_t)h * 64 * 4096;

    if (tid == 0) {
#pragma unroll
        for (int i = 0; i < 4; i++) mbar_init(bar[i], 1);
    }
    __syncthreads();

    if (tid == 0) {
#pragma unroll
        for (int i = 0; i < 4; i++) {
            mbar_arrive_expect(bar[i], 8192);
            bulk_g2s(smem_u32(&sK[i][0]), Ksrc + (size_t)i * 4096, 8192, bar[i]);
        }
    }

    // A fragments (fp16 Q), register-resident: 4 k-steps x 4 regs
    uint32_t a[4][4];
    {
        const float* QA = g_Qh + ((size_t)h * N_NODES + qA) * 64;
        const float* QB = QA + 8 * 64;
#pragma unroll
        for (int s = 0; s < 4; s++) {
            const int c = s * 16 + 2 * l4;
            a[s][0] = pack_h2(QA[c],     QA[c + 1]);
            a[s][1] = pack_h2(QB[c],     QB[c + 1]);
            a[s][2] = pack_h2(QA[c + 8], QA[c + 9]);
            a[s][3] = pack_h2(QB[c + 8], QB[c + 9]);
        }
    }

    float bestA = -3.3e38f, best2A = -3.3e38f;
    float bestB = -3.3e38f, best2B = -3.3e38f;
    int   bkA = 0, bkB = 0;

    for (int t = 0; t < 64; t++) {
        const int buf = t & 3;
        const int ph  = (t >> 2) & 1;
        mbar_wait(bar[buf], ph);

        // mask -> accumulator init (0 allowed, -3e38 masked)
        const unsigned w0A = g_adjbits[(size_t)(2 * t)     * N_NODES + qA];
        const unsigned w1A = g_adjbits[(size_t)(2 * t + 1) * N_NODES + qA];
        const unsigned w0B = g_adjbits[(size_t)(2 * t)     * N_NODES + qB];
        const unsigned w1B = g_adjbits[(size_t)(2 * t + 1) * N_NODES + qB];

        float acc[8][4];
#pragma unroll
        for (int nf = 0; nf < 8; nf++) {
            const unsigned wdA = (nf < 4) ? w0A : w1A;
            const unsigned wdB = (nf < 4) ? w0B : w1B;
            const int sh = (nf & 3) * 8 + l4 * 2;
            acc[nf][0] = ((wdA >> sh) & 1u)       ? 0.0f : -3e38f;
            acc[nf][1] = ((wdA >> (sh + 1)) & 1u) ? 0.0f : -3e38f;
            acc[nf][2] = ((wdB >> sh) & 1u)       ? 0.0f : -3e38f;
            acc[nf][3] = ((wdB >> (sh + 1)) & 1u) ? 0.0f : -3e38f;
        }

        const __half* kb = &sK[buf][0];
#pragma unroll
        for (int nf = 0; nf < 8; nf++) {
#pragma unroll
            for (int sp = 0; sp < 2; sp++) {
                const uint4 bb = *(const uint4*)&kb[(size_t)(((nf * 2 + sp) * 32 + lane)) * 8];
                mma16(acc[nf], a[2 * sp],     bb.x, bb.y);
                mma16(acc[nf], a[2 * sp + 1], bb.z, bb.w);
            }
        }
        __syncthreads();                  // all warps done with sK[buf]
        if (tid == 0 && t + 4 < 64) {
            mbar_arrive_expect(bar[buf], 8192);
            bulk_g2s(smem_u32(&sK[buf][0]), Ksrc + (size_t)(t + 4) * 4096, 8192, bar[buf]);
        }

        // masked max trees (values already masked via acc init)
        float tA = fmaxf(acc[0][0], acc[0][1]);
        float tB = fmaxf(acc[0][2], acc[0][3]);
#pragma unroll
        for (int nf = 1; nf < 8; nf++) {
            tA = fmaxf(tA, fmaxf(acc[nf][0], acc[nf][1]));
            tB = fmaxf(tB, fmaxf(acc[nf][2], acc[nf][3]));
        }
        if (tA > bestA) rare2(acc, 0, t, l4, tA, bestA, best2A, bkA);
        else            best2A = fmaxf(best2A, tA);
        if (tB > bestB) rare2(acc, 2, t, l4, tB, bestB, best2B, bkB);
        else            best2B = fmaxf(best2B, tB);
    }

    // quad reduction (lanes sharing the same q rows)
#pragma unroll
    for (int off = 1; off < 4; off <<= 1) {
        float ob  = __shfl_xor_sync(0xffffffffu, bestA, off);
        int   obk = __shfl_xor_sync(0xffffffffu, bkA,  off);
        float ob2 = __shfl_xor_sync(0xffffffffu, best2A, off);
        best2A = fmaxf(fmaxf(best2A, ob2), fminf(bestA, ob));
        if (ob > bestA || (ob == bestA && obk < bkA)) { bestA = ob; bkA = obk; }

        ob  = __shfl_xor_sync(0xffffffffu, bestB, off);
        obk = __shfl_xor_sync(0xffffffffu, bkB,  off);
        ob2 = __shfl_xor_sync(0xffffffffu, best2B, off);
        best2B = fmaxf(fmaxf(best2B, ob2), fminf(bestB, ob));
        if (ob > bestB || (ob == bestB && obk < bkB)) { bestB = ob; bkB = obk; }
    }

    if (l4 == 0) {
        const int hqA = h * N_NODES + qA;
        const int hqB = h * N_NODES + qB;
        g_argmax[hqA] = bkA;
        g_argmax[hqB] = bkB;
        if (bestA - best2A < BAND) g_fixlist[atomicAdd(&g_fixcount, 1)] = hqA;
        if (bestB - best2B < BAND) g_fixlist[atomicAdd(&g_fixcount, 1)] = hqB;
    }
}

// ============================================================================
// Pass 2: exact fp32 re-argmax of flagged rows (grid-stride over flags).
// ============================================================================
__global__ __launch_bounds__(256) void rescan() {
    __shared__ float s_best[8];
    __shared__ int   s_bk[8];
    const int nfix = g_fixcount;
    const int tid = threadIdx.x, lane = tid & 31, wrp = tid >> 5;

    for (int i = blockIdx.x; i < nfix; i += gridDim.x) {
        const int hq = g_fixlist[i];
        const int h = hq >> 12, q = hq & (N_NODES - 1);
        const float* Qr = g_Qh + ((size_t)h * N_NODES + q) * 64;
        float qv[64];
#pragma unroll
        for (int j = 0; j < 16; j++) {
            float4 v = *(const float4*)&Qr[j * 4];
            qv[j*4] = v.x; qv[j*4+1] = v.y; qv[j*4+2] = v.z; qv[j*4+3] = v.w;
        }

        float best = -3e38f;
        int   bk   = 1 << 30;
        for (int k = tid; k < N_NODES; k += 256) {
            const unsigned wd = g_adjbits[(k >> 5) * N_NODES + q];
            if ((wd >> (k & 31)) & 1u) {
                const float* Kr = g_Kh + ((size_t)h * N_NODES + k) * 64;
                float d = 0.f;
#pragma unroll
                for (int j = 0; j < 16; j++) {
                    float4 v = *(const float4*)&Kr[j * 4];
                    d += qv[j*4] * v.x + qv[j*4+1] * v.y
                       + qv[j*4+2] * v.z + qv[j*4+3] * v.w;
                }
                if (d > best || (d == best && k < bk)) { best = d; bk = k; }
            }
        }
#pragma unroll
        for (int off = 16; off > 0; off >>= 1) {
            float ob  = __shfl_xor_sync(0xffffffffu, best, off);
            int   obk = __shfl_xor_sync(0xffffffffu, bk, off);
            if (ob > best || (ob == best && obk < bk)) { best = ob; bk = obk; }
        }
        if (lane == 0) { s_best[wrp] = best; s_bk[wrp] = bk; }
        __syncthreads();
        if (tid == 0) {
            float b = s_best[0]; int k = s_bk[0];
#pragma unroll
            for (int j = 1; j < 8; j++)
                if (s_best[j] > b || (s_best[j] == b && s_bk[j] < k)) {
                    b = s_best[j]; k = s_bk[j];
                }
            g_argmax[hq] = k;
        }
        __syncthreads();
    }
}

// ============================================================================
// out[q, h*64+d] = V[argmax(h,q), h*64+d] / HEADS
// ============================================================================
__global__ __launch_bounds__(256) void gather_out(float* __restrict__ out) {
    const int idx = blockIdx.x * blockDim.x + threadIdx.x;
    const int q   = idx >> 7;
    const int c4  = idx & 127;
    const int h   = c4 >> 4;
    const int k   = g_argmax[h * N_NODES + q];
    float4 t = *(const float4*)&g_V[(size_t)k * 512 + c4 * 4];
    float4 v = make_float4(t.x * 0.125f, t.y * 0.125f, t.z * 0.125f, t.w * 0.125f);
    *(float4*)&out[(size_t)idx * 4] = v;
}

// ============================================================================
extern "C" void kernel_launch(void* const* d_in, const int* in_sizes, int n_in,
                              void* d_out, int out_size)
{
    const float* x   = (const float*)d_in[0];
    const int*   adj = (const int*)d_in[1];
    const float* WQ  = (const float*)d_in[2];
    const float* WK  = (const float*)d_in[3];
    const float* WV  = (const float*)d_in[4];
    float* out = (float*)d_out;

    cudaFuncSetAttribute(qkv_gemm,
                         cudaFuncAttributeMaxDynamicSharedMemorySize, QKV_SMEM);

    dim3 tb(32, 8);
    transpose_xw<<<dim3(IN_FEAT / 32, 176), tb>>>(x, WQ, WK, WV);
    adj_to_bits<<<N_NODES / 8, 256>>>(adj);

    qkv_gemm<<<dim3(E3 / 128, N_NODES / 128), 512, QKV_SMEM>>>();

    convert_k16<<<dim3(64, HEADS), 256>>>();

    score_mma<<<dim3(N_NODES / 64, HEADS), 128>>>();

    rescan<<<512, 256>>>();

    gather_out<<<(N_NODES * 512 / 4) / 256, 256>>>(out);
}

// round 10
// speedup vs baseline: 1.6213x; 1.0162x over previous
#include <cuda_runtime.h>
#include <cuda_fp16.h>
#include <cstdint>

#define N_NODES 4096
#define IN_FEAT 512
#define E3      1536
#define HEADS   8
#define HEAD_DIM 64
#define BAND    0.075f

// ---------------- scratch (static device globals: no allocation) ------------
__device__ float    g_xT[IN_FEAT * N_NODES];     // [k][m]
__device__ float    g_WT[IN_FEAT * E3];          // [k][n]
__device__ float    g_Qh[HEADS * N_NODES * 64];  // head-major [h][node][d]
__device__ float    g_Kh[HEADS * N_NODES * 64];
__device__ __half   g_Kp16[HEADS * 64 * 4096];   // fragment-PAIRED fp16 tile images
__device__ float    g_V[N_NODES * 512];          // node-major
__device__ unsigned g_adjbits[128 * N_NODES];    // [word][q]
__device__ int      g_argmax[HEADS * N_NODES];
__device__ int      g_fixcount;
__device__ int      g_fixlist[HEADS * N_NODES];

// ---------------- packed fp32x2 helpers (qkv gemm) ---------------------------
__device__ __forceinline__ unsigned long long pack2(float lo, float hi) {
    unsigned long long r;
    asm("mov.b64 %0, {%1, %2};" : "=l"(r) : "f"(lo), "f"(hi));
    return r;
}
__device__ __forceinline__ void unpack2(unsigned long long v, float& lo, float& hi) {
    asm("mov.b64 {%0, %1}, %2;" : "=f"(lo), "=f"(hi) : "l"(v));
}
__device__ __forceinline__ unsigned long long fma2(unsigned long long a,
                                                   unsigned long long b,
                                                   unsigned long long c) {
    unsigned long long d;
    asm("fma.rn.f32x2 %0, %1, %2, %3;" : "=l"(d) : "l"(a), "l"(b), "l"(c));
    return d;
}

// ---------------- mbarrier + bulk-copy helpers --------------------------------
__device__ __forceinline__ uint32_t smem_u32(const void* p) {
    uint32_t a;
    asm("{ .reg .u64 t; cvta.to.shared.u64 t, %1; cvt.u32.u64 %0, t; }"
        : "=r"(a) : "l"(p));
    return a;
}
__device__ __forceinline__ void mbar_init(uint32_t bar, uint32_t cnt) {
    asm volatile("mbarrier.init.shared.b64 [%0], %1;" :: "r"(bar), "r"(cnt) : "memory");
}
__device__ __forceinline__ void mbar_arrive_expect(uint32_t bar, uint32_t bytes) {
    asm volatile("mbarrier.arrive.expect_tx.shared.b64 _, [%0], %1;"
                 :: "r"(bar), "r"(bytes) : "memory");
}
__device__ __forceinline__ void bulk_g2s(uint32_t dst, const void* src,
                                         uint32_t bytes, uint32_t bar) {
    asm volatile(
        "cp.async.bulk.shared::cluster.global.mbarrier::complete_tx::bytes "
        "[%0], [%1], %2, [%3];"
        :: "r"(dst), "l"(src), "r"(bytes), "r"(bar) : "memory");
}
__device__ __forceinline__ void mbar_wait(uint32_t bar, uint32_t parity) {
    asm volatile(
        "{\n\t"
        ".reg .pred P;\n\t"
        "WL_%=:\n\t"
        "mbarrier.try_wait.parity.acquire.cta.shared::cta.b64 P, [%0], %1, 0x989680;\n\t"
        "@P bra WD_%=;\n\t"
        "bra WL_%=;\n\t"
        "WD_%=:\n\t"
        "}"
        :: "r"(bar), "r"(parity) : "memory");
}

// ---------------- fp16 MMA helpers --------------------------------------------
__device__ __forceinline__ uint32_t pack_h2(float x, float y) {
    __half2 v = __floats2half2_rn(x, y);
    return *reinterpret_cast<uint32_t*>(&v);
}
__device__ __forceinline__ void mma16(float* d, const uint32_t* a,
                                      uint32_t b0, uint32_t b1) {
    asm("mma.sync.aligned.m16n8k16.row.col.f32.f16.f16.f32 "
        "{%0,%1,%2,%3}, {%4,%5,%6,%7}, {%8,%9}, {%0,%1,%2,%3};"
        : "+f"(d[0]), "+f"(d[1]), "+f"(d[2]), "+f"(d[3])
        : "r"(a[0]), "r"(a[1]), "r"(a[2]), "r"(a[3]), "r"(b0), "r"(b1));
}

// ============================================================================
// prep: merged transposes + adj bitmask in ONE launch (disjoint y-ranges).
//   y <  128 : x transpose tile
//   y <  176 : W{Q,K,V} transpose tile
//   y >= 176 : adj -> bitmask (8 q rows per block, warp per row)
// ============================================================================
__global__ __launch_bounds__(256) void prep(const float* __restrict__ x,
                                            const float* __restrict__ WQ,
                                            const float* __restrict__ WK,
                                            const float* __restrict__ WV,
                                            const int* __restrict__ adj) {
    __shared__ float t[32][33];
    const int txx = threadIdx.x, tyy = threadIdx.y;
    const int bx = blockIdx.x * 32;

    if (blockIdx.y < 128) {
        const int by = blockIdx.y * 32;
#pragma unroll
        for (int i = tyy; i < 32; i += 8)
            t[i][txx] = x[(size_t)(by + i) * IN_FEAT + bx + txx];
        __syncthreads();
#pragma unroll
        for (int i = tyy; i < 32; i += 8)
            g_xT[(size_t)(bx + i) * N_NODES + by + txx] = t[txx][i];
    } else if (blockIdx.y < 176) {
        const int yy = blockIdx.y - 128;
        const int wsel = yy >> 4;                 // 0..2
        const int by = (yy & 15) * 32;
        const float* W = (wsel == 0) ? WQ : ((wsel == 1) ? WK : WV);
#pragma unroll
        for (int i = tyy; i < 32; i += 8)
            t[i][txx] = W[(size_t)(by + i) * IN_FEAT + bx + txx];
        __syncthreads();
#pragma unroll
        for (int i = tyy; i < 32; i += 8)
            g_WT[(size_t)(bx + i) * E3 + wsel * 512 + by + txx] = t[txx][i];
    } else {
        const int q = ((blockIdx.y - 176) * 16 + blockIdx.x) * 8 + tyy;
        const int* row = adj + (size_t)q * N_NODES;
#pragma unroll 4
        for (int w = 0; w < 128; w++) {
            unsigned m = __ballot_sync(0xffffffffu, row[w * 32 + txx] > 0);
            if (txx == 0) g_adjbits[w * N_NODES + q] = m;
        }
    }
}

// ============================================================================
// QKV GEMM (fp32-exact, at its f32x2 floor).  K blocks additionally emit the
// fp16 fragment-paired tile image straight from registers (replaces the old
// convert_k16 kernel; identical byte layout).
// ============================================================================
#define QKV_KT 64
#define QKV_SMEM (4 * QKV_KT * 128 * 4)

__device__ __forceinline__ void qkv_issue(int t, int m0, int n0, int tid,
                                          float* As, float* Bs,
                                          uint32_t bar0, uint32_t bar1) {
    if (tid < 128) {
        const int buf = t & 1;
        const uint32_t bar = buf ? bar1 : bar0;
        mbar_arrive_expect(bar, 512);
        const int row = tid & 63;
        const int k   = t * QKV_KT + row;
        if (tid < 64) {
            bulk_g2s(smem_u32(&As[buf * QKV_KT * 128 + row * 128]),
                     &g_xT[(size_t)k * N_NODES + m0], 512, bar);
        } else {
            bulk_g2s(smem_u32(&Bs[buf * QKV_KT * 128 + row * 128]),
                     &g_WT[(size_t)k * E3 + n0], 512, bar);
        }
    }
}

__global__ __launch_bounds__(512, 1) void qkv_gemm() {
    extern __shared__ float smem[];
    float* As = smem;
    float* Bs = smem + 2 * QKV_KT * 128;
    __shared__ __align__(8) unsigned long long mbar[2];

    const int tid = threadIdx.x;
    const int tx  = tid & 31;
    const int ty  = tid >> 5;
    const int n0  = blockIdx.x * 128;
    const int m0  = blockIdx.y * 128;
    const uint32_t bar0 = smem_u32(&mbar[0]);
    const uint32_t bar1 = smem_u32(&mbar[1]);

    if (blockIdx.x == 0 && blockIdx.y == 0 && tid == 0) g_fixcount = 0;

    if (tid == 0) { mbar_init(bar0, 128); mbar_init(bar1, 128); }
    __syncthreads();

    qkv_issue(0, m0, n0, tid, As, Bs, bar0, bar1);
    qkv_issue(1, m0, n0, tid, As, Bs, bar0, bar1);

    unsigned long long c[4][4];
#pragma unroll
    for (int i = 0; i < 4; i++)
#pragma unroll
        for (int j = 0; j < 4; j++) c[i][j] = 0ULL;

    const int ntiles = IN_FEAT / QKV_KT;
    for (int t = 0; t < ntiles; t++) {
        const int buf = t & 1;
        mbar_wait(buf ? bar1 : bar0, (t >> 1) & 1);
        const float* a = As + buf * QKV_KT * 128;
        const float* b = Bs + buf * QKV_KT * 128;
#pragma unroll 8
        for (int k = 0; k < QKV_KT; k++) {
            const ulonglong2* ap = (const ulonglong2*)&a[k * 128 + ty * 8];
            ulonglong2 a01 = ap[0];
            ulonglong2 a23 = ap[1];
            float4 bv = *(const float4*)&b[k * 128 + tx * 4];
            unsigned long long bd[4];
            bd[0] = pack2(bv.x, bv.x);
            bd[1] = pack2(bv.y, bv.y);
            bd[2] = pack2(bv.z, bv.z);
            bd[3] = pack2(bv.w, bv.w);
#pragma unroll
            for (int j = 0; j < 4; j++) {
                c[0][j] = fma2(a01.x, bd[j], c[0][j]);
                c[1][j] = fma2(a01.y, bd[j], c[1][j]);
                c[2][j] = fma2(a23.x, bd[j], c[2][j]);
                c[3][j] = fma2(a23.y, bd[j], c[3][j]);
            }
        }
        __syncthreads();
        if (t + 2 < ntiles) qkv_issue(t + 2, m0, n0, tid, As, Bs, bar0, bar1);
    }

    const int col = (n0 & 511) + tx * 4;
    float* pb;
    size_t rs;
    const bool isK = (n0 >= 512) && (n0 < 1024);
    if (n0 < 512)  { pb = g_Qh + (size_t)(col >> 6) * (N_NODES * 64) + (col & 63); rs = 64; }
    else if (isK)  { pb = g_Kh + (size_t)(col >> 6) * (N_NODES * 64) + (col & 63); rs = 64; }
    else           { pb = g_V + col; rs = 512; }

    // fragment-image coords (constant per thread; used only for K blocks)
    const int hh = col >> 6;
    const int d0 = col & 63;
    const int sp = d0 >> 5;
    const int jj = (d0 & 31) >> 3;
    const int lp = (d0 & 7) >> 1;            // 0 or 2

#pragma unroll
    for (int mp = 0; mp < 4; mp++) {
        float lo0, hi0, lo1, hi1, lo2, hi2, lo3, hi3;
        unpack2(c[mp][0], lo0, hi0);
        unpack2(c[mp][1], lo1, hi1);
        unpack2(c[mp][2], lo2, hi2);
        unpack2(c[mp][3], lo3, hi3);
        const int row0 = m0 + ty * 8 + mp * 2;
        *(float4*)&pb[(size_t)row0 * rs]       = make_float4(lo0, lo1, lo2, lo3);
        *(float4*)&pb[(size_t)(row0 + 1) * rs] = make_float4(hi0, hi1, hi2, hi3);

        if (isK) {
            // node row0 (lo values) and row0+1 (hi values)
#pragma unroll
            for (int r = 0; r < 2; r++) {
                const int node = row0 + r;
                const int kk = node & 63;
                const int kt = node >> 6;
                __half2* dst = (__half2*)(g_Kp16 + (size_t)(hh * 64 + kt) * 4096);
                const int lane = ((kk & 7) << 2) | lp;
                const int idx  = (((kk >> 3) * 2 + sp) * 32 + lane) * 4 + jj;
                if (r == 0) {
                    dst[idx]     = __floats2half2_rn(lo0, lo1);
                    dst[idx + 4] = __floats2half2_rn(lo2, lo3);
                } else {
                    dst[idx]     = __floats2half2_rn(hi0, hi1);
                    dst[idx + 4] = __floats2half2_rn(hi2, hi3);
                }
            }
        }
    }
}

// ============================================================================
// rare index recovery (R7, validated)
// ============================================================================
__device__ __forceinline__ void rare2(const float (&acc)[8][4], int cofs,
                                      int t, int l4, float tmax,
                                      float& best, float& best2, int& bk) {
    float sec = -3e38f;
    int   idx = bk;
    bool  taken = false;
#pragma unroll
    for (int nf = 0; nf < 8; nf++)
#pragma unroll
        for (int c = 0; c < 2; c++) {
            const float v = acc[nf][cofs + c];
            if (v == tmax && !taken) {
                taken = true;
                idx = t * 64 + nf * 8 + l4 * 2 + c;
            } else {
                sec = fmaxf(sec, v);
            }
        }
    best2 = fmaxf(best2, fmaxf(best, sec));
    best  = tmax;
    bk    = idx;
}

// ============================================================================
// Score argmax via mma.sync m16n8k16.f16; mask folded into accumulator init;
// 4-deep bulk-copy ring; paired-fragment LDS.128 B loads.
// Block = 64 q x 1 head, 4 warps.  (Measured at 100.6% of the shared-FMA-pipe
// MAC floor — do not add per-score scalar work here.)
// ============================================================================
__global__ __launch_bounds__(128, 4) void score_mma() {
    __shared__ __align__(16) __half sK[4][4096];  // 4 x 8 KB ring
    __shared__ __align__(8) unsigned long long s_bar[4];

    const int tid  = threadIdx.x;
    const int w    = tid >> 5;
    const int lane = tid & 31;
    const int g    = lane >> 2;
    const int l4   = lane & 3;
    const int h    = blockIdx.y;
    const int qt   = blockIdx.x;
    const int qA   = qt * 64 + w * 16 + g;
    const int qB   = qA + 8;

    uint32_t bar[4];
#pragma unroll
    for (int i = 0; i < 4; i++) bar[i] = smem_u32(&s_bar[i]);
    const __half* Ksrc = g_Kp16 + (size_t)h * 64 * 4096;

    if (tid == 0) {
#pragma unroll
        for (int i = 0; i < 4; i++) mbar_init(bar[i], 1);
    }
    __syncthreads();

    if (tid == 0) {
#pragma unroll
        for (int i = 0; i < 4; i++) {
            mbar_arrive_expect(bar[i], 8192);
            bulk_g2s(smem_u32(&sK[i][0]), Ksrc + (size_t)i * 4096, 8192, bar[i]);
        }
    }

    // A fragments (fp16 Q), register-resident: 4 k-steps x 4 regs
    uint32_t a[4][4];
    {
        const float* QA = g_Qh + ((size_t)h * N_NODES + qA) * 64;
        const float* QB = QA + 8 * 64;
#pragma unroll
        for (int s = 0; s < 4; s++) {
            const int c = s * 16 + 2 * l4;
            a[s][0] = pack_h2(QA[c],     QA[c + 1]);
            a[s][1] = pack_h2(QB[c],     QB[c + 1]);
            a[s][2] = pack_h2(QA[c + 8], QA[c + 9]);
            a[s][3] = pack_h2(QB[c + 8], QB[c + 9]);
        }
    }

    float bestA = -3.3e38f, best2A = -3.3e38f;
    float bestB = -3.3e38f, best2B = -3.3e38f;
    int   bkA = 0, bkB = 0;

    for (int t = 0; t < 64; t++) {
        const int buf = t & 3;
        const int ph  = (t >> 2) & 1;
        mbar_wait(bar[buf], ph);

        // mask -> accumulator init (0 allowed, -3e38 masked)
        const unsigned w0A = g_adjbits[(size_t)(2 * t)     * N_NODES + qA];
        const unsigned w1A = g_adjbits[(size_t)(2 * t + 1) * N_NODES + qA];
        const unsigned w0B = g_adjbits[(size_t)(2 * t)     * N_NODES + qB];
        const unsigned w1B = g_adjbits[(size_t)(2 * t + 1) * N_NODES + qB];

        float acc[8][4];
#pragma unroll
        for (int nf = 0; nf < 8; nf++) {
            const unsigned wdA = (nf < 4) ? w0A : w1A;
            const unsigned wdB = (nf < 4) ? w0B : w1B;
            const int sh = (nf & 3) * 8 + l4 * 2;
            acc[nf][0] = ((wdA >> sh) & 1u)       ? 0.0f : -3e38f;
            acc[nf][1] = ((wdA >> (sh + 1)) & 1u) ? 0.0f : -3e38f;
            acc[nf][2] = ((wdB >> sh) & 1u)       ? 0.0f : -3e38f;
            acc[nf][3] = ((wdB >> (sh + 1)) & 1u) ? 0.0f : -3e38f;
        }

        const __half* kb = &sK[buf][0];
#pragma unroll
        for (int nf = 0; nf < 8; nf++) {
#pragma unroll
            for (int sp = 0; sp < 2; sp++) {
                const uint4 bb = *(const uint4*)&kb[(size_t)(((nf * 2 + sp) * 32 + lane)) * 8];
                mma16(acc[nf], a[2 * sp],     bb.x, bb.y);
                mma16(acc[nf], a[2 * sp + 1], bb.z, bb.w);
            }
        }
        __syncthreads();                  // all warps done with sK[buf]
        if (tid == 0 && t + 4 < 64) {
            mbar_arrive_expect(bar[buf], 8192);
            bulk_g2s(smem_u32(&sK[buf][0]), Ksrc + (size_t)(t + 4) * 4096, 8192, bar[buf]);
        }

        // masked max trees (values already masked via acc init)
        float tA = fmaxf(acc[0][0], acc[0][1]);
        float tB = fmaxf(acc[0][2], acc[0][3]);
#pragma unroll
        for (int nf = 1; nf < 8; nf++) {
            tA = fmaxf(tA, fmaxf(acc[nf][0], acc[nf][1]));
            tB = fmaxf(tB, fmaxf(acc[nf][2], acc[nf][3]));
        }
        if (tA > bestA) rare2(acc, 0, t, l4, tA, bestA, best2A, bkA);
        else            best2A = fmaxf(best2A, tA);
        if (tB > bestB) rare2(acc, 2, t, l4, tB, bestB, best2B, bkB);
        else            best2B = fmaxf(best2B, tB);
    }

    // quad reduction (lanes sharing the same q rows)
#pragma unroll
    for (int off = 1; off < 4; off <<= 1) {
        float ob  = __shfl_xor_sync(0xffffffffu, bestA, off);
        int   obk = __shfl_xor_sync(0xffffffffu, bkA,  off);
        float ob2 = __shfl_xor_sync(0xffffffffu, best2A, off);
        best2A = fmaxf(fmaxf(best2A, ob2), fminf(bestA, ob));
        if (ob > bestA || (ob == bestA && obk < bkA)) { bestA = ob; bkA = obk; }

        ob  = __shfl_xor_sync(0xffffffffu, bestB, off);
        obk = __shfl_xor_sync(0xffffffffu, bkB,  off);
        ob2 = __shfl_xor_sync(0xffffffffu, best2B, off);
        best2B = fmaxf(fmaxf(best2B, ob2), fminf(bestB, ob));
        if (ob > bestB || (ob == bestB && obk < bkB)) { bestB = ob; bkB = obk; }
    }

    if (l4 == 0) {
        const int hqA = h * N_NODES + qA;
        const int hqB = h * N_NODES + qB;
        g_argmax[hqA] = bkA;
        g_argmax[hqB] = bkB;
        if (bestA - best2A < BAND) g_fixlist[atomicAdd(&g_fixcount, 1)] = hqA;
        if (bestB - best2B < BAND) g_fixlist[atomicAdd(&g_fixcount, 1)] = hqB;
    }
}

// ============================================================================
// Pass 2: exact fp32 re-argmax of flagged rows (grid-stride over flags).
// ============================================================================
__global__ __launch_bounds__(256) void rescan() {
    __shared__ float s_best[8];
    __shared__ int   s_bk[8];
    const int nfix = g_fixcount;
    const int tid = threadIdx.x, lane = tid & 31, wrp = tid >> 5;

    for (int i = blockIdx.x; i < nfix; i += gridDim.x) {
        const int hq = g_fixlist[i];
        const int h = hq >> 12, q = hq & (N_NODES - 1);
        const float* Qr = g_Qh + ((size_t)h * N_NODES + q) * 64;
        float qv[64];
#pragma unroll
        for (int j = 0; j < 16; j++) {
            float4 v = *(const float4*)&Qr[j * 4];
            qv[j*4] = v.x; qv[j*4+1] = v.y; qv[j*4+2] = v.z; qv[j*4+3] = v.w;
        }

        float best = -3e38f;
        int   bk   = 1 << 30;
        for (int k = tid; k < N_NODES; k += 256) {
            const unsigned wd = g_adjbits[(k >> 5) * N_NODES + q];
            if ((wd >> (k & 31)) & 1u) {
                const float* Kr = g_Kh + ((size_t)h * N_NODES + k) * 64;
                float d = 0.f;
#pragma unroll
                for (int j = 0; j < 16; j++) {
                    float4 v = *(const float4*)&Kr[j * 4];
                    d += qv[j*4] * v.x + qv[j*4+1] * v.y
                       + qv[j*4+2] * v.z + qv[j*4+3] * v.w;
                }
                if (d > best || (d == best && k < bk)) { best = d; bk = k; }
            }
        }
#pragma unroll
        for (int off = 16; off > 0; off >>= 1) {
            float ob  = __shfl_xor_sync(0xffffffffu, best, off);
            int   obk = __shfl_xor_sync(0xffffffffu, bk, off);
            if (ob > best || (ob == best && obk < bk)) { best = ob; bk = obk; }
        }
        if (lane == 0) { s_best[wrp] = best; s_bk[wrp] = bk; }
        __syncthreads();
        if (tid == 0) {
            float b = s_best[0]; int k = s_bk[0];
#pragma unroll
            for (int j = 1; j < 8; j++)
                if (s_best[j] > b || (s_best[j] == b && s_bk[j] < k)) {
                    b = s_best[j]; k = s_bk[j];
                }
            g_argmax[hq] = k;
        }
        __syncthreads();
    }
}

// ============================================================================
// out[q, h*64+d] = V[argmax(h,q), h*64+d] / HEADS
// ============================================================================
__global__ __launch_bounds__(256) void gather_out(float* __restrict__ out) {
    const int idx = blockIdx.x * blockDim.x + threadIdx.x;
    const int q   = idx >> 7;
    const int c4  = idx & 127;
    const int h   = c4 >> 4;
    const int k   = g_argmax[h * N_NODES + q];
    float4 t = *(const float4*)&g_V[(size_t)k * 512 + c4 * 4];
    float4 v = make_float4(t.x * 0.125f, t.y * 0.125f, t.z * 0.125f, t.w * 0.125f);
    *(float4*)&out[(size_t)idx * 4] = v;
}

// ============================================================================
extern "C" void kernel_launch(void* const* d_in, const int* in_sizes, int n_in,
                              void* d_out, int out_size)
{
    const float* x   = (const float*)d_in[0];
    const int*   adj = (const int*)d_in[1];
    const float* WQ  = (const float*)d_in[2];
    const float* WK  = (const float*)d_in[3];
    const float* WV  = (const float*)d_in[4];
    float* out = (float*)d_out;

    cudaFuncSetAttribute(qkv_gemm,
                         cudaFuncAttributeMaxDynamicSharedMemorySize, QKV_SMEM);

    dim3 tb(32, 8);
    prep<<<dim3(16, 208), tb>>>(x, WQ, WK, WV, adj);

    qkv_gemm<<<dim3(E3 / 128, N_NODES / 128), 512, QKV_SMEM>>>();

    score_mma<<<dim3(N_NODES / 64, HEADS), 128>>>();

    rescan<<<512, 256>>>();

    gather_out<<<(N_NODES * 512 / 4) / 256, 256>>>(out);
}

// round 11
// speedup vs baseline: 2.1429x; 1.3218x over previous
#include <cuda_runtime.h>
#include <cuda_fp16.h>
#include <cstdint>

#define N_NODES 4096
#define IN_FEAT 512
#define E3      1536
#define HEADS   8
#define HEAD_DIM 64
#define BAND    0.075f

// ---------------- scratch (static device globals: no allocation) ------------
__device__ float    g_xT[IN_FEAT * N_NODES];     // [k][m]
__device__ float    g_WT[IN_FEAT * E3];          // [k][n]
__device__ float    g_Qh[HEADS * N_NODES * 64];  // head-major [h][node][d]
__device__ float    g_Kh[HEADS * N_NODES * 64];
__device__ float    g_KhT[HEADS * 64 * N_NODES]; // [h][d][node]  (rescan)
__device__ __half   g_Kp16[HEADS * 64 * 4096];   // fragment-PAIRED fp16 tile images
__device__ float    g_V[N_NODES * 512];          // node-major
__device__ unsigned g_adjbits[128 * N_NODES];    // [word][q]
__device__ int      g_argmax[HEADS * N_NODES];
__device__ int      g_fixcount;
__device__ int      g_fixlist[HEADS * N_NODES];

// ---------------- packed fp32x2 helpers (qkv gemm) ---------------------------
__device__ __forceinline__ unsigned long long pack2(float lo, float hi) {
    unsigned long long r;
    asm("mov.b64 %0, {%1, %2};" : "=l"(r) : "f"(lo), "f"(hi));
    return r;
}
__device__ __forceinline__ void unpack2(unsigned long long v, float& lo, float& hi) {
    asm("mov.b64 {%0, %1}, %2;" : "=f"(lo), "=f"(hi) : "l"(v));
}
__device__ __forceinline__ unsigned long long fma2(unsigned long long a,
                                                   unsigned long long b,
                                                   unsigned long long c) {
    unsigned long long d;
    asm("fma.rn.f32x2 %0, %1, %2, %3;" : "=l"(d) : "l"(a), "l"(b), "l"(c));
    return d;
}

// ---------------- mbarrier + bulk-copy helpers --------------------------------
__device__ __forceinline__ uint32_t smem_u32(const void* p) {
    uint32_t a;
    asm("{ .reg .u64 t; cvta.to.shared.u64 t, %1; cvt.u32.u64 %0, t; }"
        : "=r"(a) : "l"(p));
    return a;
}
__device__ __forceinline__ void mbar_init(uint32_t bar, uint32_t cnt) {
    asm volatile("mbarrier.init.shared.b64 [%0], %1;" :: "r"(bar), "r"(cnt) : "memory");
}
__device__ __forceinline__ void mbar_arrive_expect(uint32_t bar, uint32_t bytes) {
    asm volatile("mbarrier.arrive.expect_tx.shared.b64 _, [%0], %1;"
                 :: "r"(bar), "r"(bytes) : "memory");
}
__device__ __forceinline__ void bulk_g2s(uint32_t dst, const void* src,
                                         uint32_t bytes, uint32_t bar) {
    asm volatile(
        "cp.async.bulk.shared::cluster.global.mbarrier::complete_tx::bytes "
        "[%0], [%1], %2, [%3];"
        :: "r"(dst), "l"(src), "r"(bytes), "r"(bar) : "memory");
}
__device__ __forceinline__ void mbar_wait(uint32_t bar, uint32_t parity) {
    asm volatile(
        "{\n\t"
        ".reg .pred P;\n\t"
        "WL_%=:\n\t"
        "mbarrier.try_wait.parity.acquire.cta.shared::cta.b64 P, [%0], %1, 0x989680;\n\t"
        "@P bra WD_%=;\n\t"
        "bra WL_%=;\n\t"
        "WD_%=:\n\t"
        "}"
        :: "r"(bar), "r"(parity) : "memory");
}

// ---------------- fp16 MMA helpers --------------------------------------------
__device__ __forceinline__ uint32_t pack_h2(float x, float y) {
    __half2 v = __floats2half2_rn(x, y);
    return *reinterpret_cast<uint32_t*>(&v);
}
__device__ __forceinline__ void mma16(float* d, const uint32_t* a,
                                      uint32_t b0, uint32_t b1) {
    asm("mma.sync.aligned.m16n8k16.row.col.f32.f16.f16.f32 "
        "{%0,%1,%2,%3}, {%4,%5,%6,%7}, {%8,%9}, {%0,%1,%2,%3};"
        : "+f"(d[0]), "+f"(d[1]), "+f"(d[2]), "+f"(d[3])
        : "r"(a[0]), "r"(a[1]), "r"(a[2]), "r"(a[3]), "r"(b0), "r"(b1));
}

// ============================================================================
// prep: merged transposes + adj bitmask in ONE launch (disjoint y-ranges).
// ============================================================================
__global__ __launch_bounds__(256) void prep(const float* __restrict__ x,
                                            const float* __restrict__ WQ,
                                            const float* __restrict__ WK,
                                            const float* __restrict__ WV,
                                            const int* __restrict__ adj) {
    __shared__ float t[32][33];
    const int txx = threadIdx.x, tyy = threadIdx.y;
    const int bx = blockIdx.x * 32;

    if (blockIdx.y < 128) {
        const int by = blockIdx.y * 32;
#pragma unroll
        for (int i = tyy; i < 32; i += 8)
            t[i][txx] = x[(size_t)(by + i) * IN_FEAT + bx + txx];
        __syncthreads();
#pragma unroll
        for (int i = tyy; i < 32; i += 8)
            g_xT[(size_t)(bx + i) * N_NODES + by + txx] = t[txx][i];
    } else if (blockIdx.y < 176) {
        const int yy = blockIdx.y - 128;
        const int wsel = yy >> 4;                 // 0..2
        const int by = (yy & 15) * 32;
        const float* W = (wsel == 0) ? WQ : ((wsel == 1) ? WK : WV);
#pragma unroll
        for (int i = tyy; i < 32; i += 8)
            t[i][txx] = W[(size_t)(by + i) * IN_FEAT + bx + txx];
        __syncthreads();
#pragma unroll
        for (int i = tyy; i < 32; i += 8)
            g_WT[(size_t)(bx + i) * E3 + wsel * 512 + by + txx] = t[txx][i];
    } else {
        const int q = ((blockIdx.y - 176) * 16 + blockIdx.x) * 8 + tyy;
        const int* row = adj + (size_t)q * N_NODES;
#pragma unroll 4
        for (int w = 0; w < 128; w++) {
            unsigned m = __ballot_sync(0xffffffffu, row[w * 32 + txx] > 0);
            if (txx == 0) g_adjbits[w * N_NODES + q] = m;
        }
    }
}

// ============================================================================
// QKV GEMM (fp32-exact).  K blocks also emit the fp16 fragment image.
// ============================================================================
#define QKV_KT 64
#define QKV_SMEM (4 * QKV_KT * 128 * 4)

__device__ __forceinline__ void qkv_issue(int t, int m0, int n0, int tid,
                                          float* As, float* Bs,
                                          uint32_t bar0, uint32_t bar1) {
    if (tid < 128) {
        const int buf = t & 1;
        const uint32_t bar = buf ? bar1 : bar0;
        mbar_arrive_expect(bar, 512);
        const int row = tid & 63;
        const int k   = t * QKV_KT + row;
        if (tid < 64) {
            bulk_g2s(smem_u32(&As[buf * QKV_KT * 128 + row * 128]),
                     &g_xT[(size_t)k * N_NODES + m0], 512, bar);
        } else {
            bulk_g2s(smem_u32(&Bs[buf * QKV_KT * 128 + row * 128]),
                     &g_WT[(size_t)k * E3 + n0], 512, bar);
        }
    }
}

__global__ __launch_bounds__(512, 1) void qkv_gemm() {
    extern __shared__ float smem[];
    float* As = smem;
    float* Bs = smem + 2 * QKV_KT * 128;
    __shared__ __align__(8) unsigned long long mbar[2];

    const int tid = threadIdx.x;
    const int tx  = tid & 31;
    const int ty  = tid >> 5;
    const int n0  = blockIdx.x * 128;
    const int m0  = blockIdx.y * 128;
    const uint32_t bar0 = smem_u32(&mbar[0]);
    const uint32_t bar1 = smem_u32(&mbar[1]);

    if (blockIdx.x == 0 && blockIdx.y == 0 && tid == 0) g_fixcount = 0;

    if (tid == 0) { mbar_init(bar0, 128); mbar_init(bar1, 128); }
    __syncthreads();

    qkv_issue(0, m0, n0, tid, As, Bs, bar0, bar1);
    qkv_issue(1, m0, n0, tid, As, Bs, bar0, bar1);

    unsigned long long c[4][4];
#pragma unroll
    for (int i = 0; i < 4; i++)
#pragma unroll
        for (int j = 0; j < 4; j++) c[i][j] = 0ULL;

    const int ntiles = IN_FEAT / QKV_KT;
    for (int t = 0; t < ntiles; t++) {
        const int buf = t & 1;
        mbar_wait(buf ? bar1 : bar0, (t >> 1) & 1);
        const float* a = As + buf * QKV_KT * 128;
        const float* b = Bs + buf * QKV_KT * 128;
#pragma unroll 8
        for (int k = 0; k < QKV_KT; k++) {
            const ulonglong2* ap = (const ulonglong2*)&a[k * 128 + ty * 8];
            ulonglong2 a01 = ap[0];
            ulonglong2 a23 = ap[1];
            float4 bv = *(const float4*)&b[k * 128 + tx * 4];
            unsigned long long bd[4];
            bd[0] = pack2(bv.x, bv.x);
            bd[1] = pack2(bv.y, bv.y);
            bd[2] = pack2(bv.z, bv.z);
            bd[3] = pack2(bv.w, bv.w);
#pragma unroll
            for (int j = 0; j < 4; j++) {
                c[0][j] = fma2(a01.x, bd[j], c[0][j]);
                c[1][j] = fma2(a01.y, bd[j], c[1][j]);
                c[2][j] = fma2(a23.x, bd[j], c[2][j]);
                c[3][j] = fma2(a23.y, bd[j], c[3][j]);
            }
        }
        __syncthreads();
        if (t + 2 < ntiles) qkv_issue(t + 2, m0, n0, tid, As, Bs, bar0, bar1);
    }

    const int col = (n0 & 511) + tx * 4;
    float* pb;
    size_t rs;
    const bool isK = (n0 >= 512) && (n0 < 1024);
    if (n0 < 512)  { pb = g_Qh + (size_t)(col >> 6) * (N_NODES * 64) + (col & 63); rs = 64; }
    else if (isK)  { pb = g_Kh + (size_t)(col >> 6) * (N_NODES * 64) + (col & 63); rs = 64; }
    else           { pb = g_V + col; rs = 512; }

    const int hh = col >> 6;
    const int d0 = col & 63;
    const int sp = d0 >> 5;
    const int jj = (d0 & 31) >> 3;
    const int lp = (d0 & 7) >> 1;

#pragma unroll
    for (int mp = 0; mp < 4; mp++) {
        float lo0, hi0, lo1, hi1, lo2, hi2, lo3, hi3;
        unpack2(c[mp][0], lo0, hi0);
        unpack2(c[mp][1], lo1, hi1);
        unpack2(c[mp][2], lo2, hi2);
        unpack2(c[mp][3], lo3, hi3);
        const int row0 = m0 + ty * 8 + mp * 2;
        *(float4*)&pb[(size_t)row0 * rs]       = make_float4(lo0, lo1, lo2, lo3);
        *(float4*)&pb[(size_t)(row0 + 1) * rs] = make_float4(hi0, hi1, hi2, hi3);

        if (isK) {
#pragma unroll
            for (int r = 0; r < 2; r++) {
                const int node = row0 + r;
                const int kk = node & 63;
                const int kt = node >> 6;
                __half2* dst = (__half2*)(g_Kp16 + (size_t)(hh * 64 + kt) * 4096);
                const int lane = ((kk & 7) << 2) | lp;
                const int idx  = (((kk >> 3) * 2 + sp) * 32 + lane) * 4 + jj;
                if (r == 0) {
                    dst[idx]     = __floats2half2_rn(lo0, lo1);
                    dst[idx + 4] = __floats2half2_rn(lo2, lo3);
                } else {
                    dst[idx]     = __floats2half2_rn(hi0, hi1);
                    dst[idx + 4] = __floats2half2_rn(hi2, hi3);
                }
            }
        }
    }
}

// ============================================================================
// K transpose for rescan:  g_Kh[h][node][d] -> g_KhT[h][d][node]
// ============================================================================
__global__ __launch_bounds__(256) void transpose_k() {
    __shared__ float t[32][33];
    const int h  = blockIdx.z;
    const int d0 = blockIdx.y * 32;
    const int n0 = blockIdx.x * 32;
    const int txx = threadIdx.x, tyy = threadIdx.y;
    const float* src = g_Kh + (size_t)h * N_NODES * 64;
#pragma unroll
    for (int i = tyy; i < 32; i += 8)
        t[i][txx] = src[(size_t)(n0 + i) * 64 + d0 + txx];
    __syncthreads();
    float* dst = g_KhT + (size_t)h * 64 * N_NODES;
#pragma unroll
    for (int i = tyy; i < 32; i += 8)
        dst[(size_t)(d0 + i) * N_NODES + n0 + txx] = t[txx][i];
}

// ============================================================================
// rare index recovery (R7, validated)
// ============================================================================
__device__ __forceinline__ void rare2(const float (&acc)[8][4], int cofs,
                                      int t, int l4, float tmax,
                                      float& best, float& best2, int& bk) {
    float sec = -3e38f;
    int   idx = bk;
    bool  taken = false;
#pragma unroll
    for (int nf = 0; nf < 8; nf++)
#pragma unroll
        for (int c = 0; c < 2; c++) {
            const float v = acc[nf][cofs + c];
            if (v == tmax && !taken) {
                taken = true;
                idx = t * 64 + nf * 8 + l4 * 2 + c;
            } else {
                sec = fmaxf(sec, v);
            }
        }
    best2 = fmaxf(best2, fmaxf(best, sec));
    best  = tmax;
    bk    = idx;
}

// ============================================================================
// Score argmax via mma.sync m16n8k16.f16 (unchanged, ~75us measured-by-budget)
// ============================================================================
__global__ __launch_bounds__(128, 4) void score_mma() {
    __shared__ __align__(16) __half sK[4][4096];
    __shared__ __align__(8) unsigned long long s_bar[4];

    const int tid  = threadIdx.x;
    const int w    = tid >> 5;
    const int lane = tid & 31;
    const int g    = lane >> 2;
    const int l4   = lane & 3;
    const int h    = blockIdx.y;
    const int qt   = blockIdx.x;
    const int qA   = qt * 64 + w * 16 + g;
    const int qB   = qA + 8;

    uint32_t bar[4];
#pragma unroll
    for (int i = 0; i < 4; i++) bar[i] = smem_u32(&s_bar[i]);
    const __half* Ksrc = g_Kp16 + (size_t)h * 64 * 4096;

    if (tid == 0) {
#pragma unroll
        for (int i = 0; i < 4; i++) mbar_init(bar[i], 1);
    }
    __syncthreads();

    if (tid == 0) {
#pragma unroll
        for (int i = 0; i < 4; i++) {
            mbar_arrive_expect(bar[i], 8192);
            bulk_g2s(smem_u32(&sK[i][0]), Ksrc + (size_t)i * 4096, 8192, bar[i]);
        }
    }

    uint32_t a[4][4];
    {
        const float* QA = g_Qh + ((size_t)h * N_NODES + qA) * 64;
        const float* QB = QA + 8 * 64;
#pragma unroll
        for (int s = 0; s < 4; s++) {
            const int c = s * 16 + 2 * l4;
            a[s][0] = pack_h2(QA[c],     QA[c + 1]);
            a[s][1] = pack_h2(QB[c],     QB[c + 1]);
            a[s][2] = pack_h2(QA[c + 8], QA[c + 9]);
            a[s][3] = pack_h2(QB[c + 8], QB[c + 9]);
        }
    }

    float bestA = -3.3e38f, best2A = -3.3e38f;
    float bestB = -3.3e38f, best2B = -3.3e38f;
    int   bkA = 0, bkB = 0;

    for (int t = 0; t < 64; t++) {
        const int buf = t & 3;
        const int ph  = (t >> 2) & 1;
        mbar_wait(bar[buf], ph);

        const unsigned w0A = g_adjbits[(size_t)(2 * t)     * N_NODES + qA];
        const unsigned w1A = g_adjbits[(size_t)(2 * t + 1) * N_NODES + qA];
        const unsigned w0B = g_adjbits[(size_t)(2 * t)     * N_NODES + qB];
        const unsigned w1B = g_adjbits[(size_t)(2 * t + 1) * N_NODES + qB];

        float acc[8][4];
#pragma unroll
        for (int nf = 0; nf < 8; nf++) {
            const unsigned wdA = (nf < 4) ? w0A : w1A;
            const unsigned wdB = (nf < 4) ? w0B : w1B;
            const int sh = (nf & 3) * 8 + l4 * 2;
            acc[nf][0] = ((wdA >> sh) & 1u)       ? 0.0f : -3e38f;
            acc[nf][1] = ((wdA >> (sh + 1)) & 1u) ? 0.0f : -3e38f;
            acc[nf][2] = ((wdB >> sh) & 1u)       ? 0.0f : -3e38f;
            acc[nf][3] = ((wdB >> (sh + 1)) & 1u) ? 0.0f : -3e38f;
        }

        const __half* kb = &sK[buf][0];
#pragma unroll
        for (int nf = 0; nf < 8; nf++) {
#pragma unroll
            for (int sp = 0; sp < 2; sp++) {
                const uint4 bb = *(const uint4*)&kb[(size_t)(((nf * 2 + sp) * 32 + lane)) * 8];
                mma16(acc[nf], a[2 * sp],     bb.x, bb.y);
                mma16(acc[nf], a[2 * sp + 1], bb.z, bb.w);
            }
        }
        __syncthreads();
        if (tid == 0 && t + 4 < 64) {
            mbar_arrive_expect(bar[buf], 8192);
            bulk_g2s(smem_u32(&sK[buf][0]), Ksrc + (size_t)(t + 4) * 4096, 8192, bar[buf]);
        }

        float tA = fmaxf(acc[0][0], acc[0][1]);
        float tB = fmaxf(acc[0][2], acc[0][3]);
#pragma unroll
        for (int nf = 1; nf < 8; nf++) {
            tA = fmaxf(tA, fmaxf(acc[nf][0], acc[nf][1]));
            tB = fmaxf(tB, fmaxf(acc[nf][2], acc[nf][3]));
        }
        if (tA > bestA) rare2(acc, 0, t, l4, tA, bestA, best2A, bkA);
        else            best2A = fmaxf(best2A, tA);
        if (tB > bestB) rare2(acc, 2, t, l4, tB, bestB, best2B, bkB);
        else            best2B = fmaxf(best2B, tB);
    }

#pragma unroll
    for (int off = 1; off < 4; off <<= 1) {
        float ob  = __shfl_xor_sync(0xffffffffu, bestA, off);
        int   obk = __shfl_xor_sync(0xffffffffu, bkA,  off);
        float ob2 = __shfl_xor_sync(0xffffffffu, best2A, off);
        best2A = fmaxf(fmaxf(best2A, ob2), fminf(bestA, ob));
        if (ob > bestA || (ob == bestA && obk < bkA)) { bestA = ob; bkA = obk; }

        ob  = __shfl_xor_sync(0xffffffffu, bestB, off);
        obk = __shfl_xor_sync(0xffffffffu, bkB,  off);
        ob2 = __shfl_xor_sync(0xffffffffu, best2B, off);
        best2B = fmaxf(fmaxf(best2B, ob2), fminf(bestB, ob));
        if (ob > bestB || (ob == bestB && obk < bkB)) { bestB = ob; bkB = obk; }
    }

    if (l4 == 0) {
        const int hqA = h * N_NODES + qA;
        const int hqB = h * N_NODES + qB;
        g_argmax[hqA] = bkA;
        g_argmax[hqB] = bkB;
        if (bestA - best2A < BAND) g_fixlist[atomicAdd(&g_fixcount, 1)] = hqA;
        if (bestB - best2B < BAND) g_fixlist[atomicAdd(&g_fixcount, 1)] = hqB;
    }
}

// ============================================================================
// Pass 2: exact fp32 re-argmax of flagged rows — COALESCED via K^T.
// Block(512 thr) per row; thread t owns keys {4t..4t+3, 2048+4t..2048+4t+3}.
// ============================================================================
__global__ __launch_bounds__(512) void rescan() {
    __shared__ float sq[64];
    __shared__ float s_best[16];
    __shared__ int   s_bk[16];
    const int nfix = g_fixcount;
    const int tid = threadIdx.x, lane = tid & 31, wrp = tid >> 5;

    for (int i = blockIdx.x; i < nfix; i += gridDim.x) {
        const int hq = g_fixlist[i];
        const int h = hq >> 12, q = hq & (N_NODES - 1);
        if (tid < 64) sq[tid] = g_Qh[((size_t)h * N_NODES + q) * 64 + tid];
        __syncthreads();

        const float4* KT = (const float4*)(g_KhT + (size_t)h * 64 * N_NODES);
        float acc[8] = {0.f, 0.f, 0.f, 0.f, 0.f, 0.f, 0.f, 0.f};
#pragma unroll 4
        for (int d = 0; d < 64; d++) {
            const float qd = sq[d];
            const float4 v0 = KT[(size_t)d * 1024 + tid];
            const float4 v1 = KT[(size_t)d * 1024 + 512 + tid];
            acc[0] += qd * v0.x; acc[1] += qd * v0.y;
            acc[2] += qd * v0.z; acc[3] += qd * v0.w;
            acc[4] += qd * v1.x; acc[5] += qd * v1.y;
            acc[6] += qd * v1.z; acc[7] += qd * v1.w;
        }

        const int k0 = tid * 4, k1 = 2048 + tid * 4;
        const unsigned w0 = g_adjbits[(size_t)(k0 >> 5) * N_NODES + q];
        const unsigned w1 = g_adjbits[(size_t)(k1 >> 5) * N_NODES + q];
        float best = -3e38f;
        int   bk   = 1 << 30;
#pragma unroll
        for (int j = 0; j < 4; j++) {
            if ((w0 >> ((k0 + j) & 31)) & 1u)
                if (acc[j] > best) { best = acc[j]; bk = k0 + j; }
        }
#pragma unroll
        for (int j = 0; j < 4; j++) {
            if ((w1 >> ((k1 + j) & 31)) & 1u)
                if (acc[4 + j] > best) { best = acc[4 + j]; bk = k1 + j; }
        }
#pragma unroll
        for (int off = 16; off > 0; off >>= 1) {
            float ob  = __shfl_xor_sync(0xffffffffu, best, off);
            int   obk = __shfl_xor_sync(0xffffffffu, bk, off);
            if (ob > best || (ob == best && obk < bk)) { best = ob; bk = obk; }
        }
        if (lane == 0) { s_best[wrp] = best; s_bk[wrp] = bk; }
        __syncthreads();
        if (tid == 0) {
            float b = s_best[0]; int k = s_bk[0];
#pragma unroll
            for (int j = 1; j < 16; j++)
                if (s_best[j] > b || (s_best[j] == b && s_bk[j] < k)) {
                    b = s_best[j]; k = s_bk[j];
                }
            g_argmax[hq] = k;
        }
        __syncthreads();
    }
}

// ============================================================================
// out[q, h*64+d] = V[argmax(h,q), h*64+d] / HEADS
// ============================================================================
__global__ __launch_bounds__(256) void gather_out(float* __restrict__ out) {
    const int idx = blockIdx.x * blockDim.x + threadIdx.x;
    const int q   = idx >> 7;
    const int c4  = idx & 127;
    const int h   = c4 >> 4;
    const int k   = g_argmax[h * N_NODES + q];
    float4 t = *(const float4*)&g_V[(size_t)k * 512 + c4 * 4];
    float4 v = make_float4(t.x * 0.125f, t.y * 0.125f, t.z * 0.125f, t.w * 0.125f);
    *(float4*)&out[(size_t)idx * 4] = v;
}

// ============================================================================
extern "C" void kernel_launch(void* const* d_in, const int* in_sizes, int n_in,
                              void* d_out, int out_size)
{
    const float* x   = (const float*)d_in[0];
    const int*   adj = (const int*)d_in[1];
    const float* WQ  = (const float*)d_in[2];
    const float* WK  = (const float*)d_in[3];
    const float* WV  = (const float*)d_in[4];
    float* out = (float*)d_out;

    cudaFuncSetAttribute(qkv_gemm,
                         cudaFuncAttributeMaxDynamicSharedMemorySize, QKV_SMEM);

    dim3 tb(32, 8);
    prep<<<dim3(16, 208), tb>>>(x, WQ, WK, WV, adj);

    qkv_gemm<<<dim3(E3 / 128, N_NODES / 128), 512, QKV_SMEM>>>();

    transpose_k<<<dim3(N_NODES / 32, 2, HEADS), tb>>>();

    score_mma<<<dim3(N_NODES / 64, HEADS), 128>>>();

    rescan<<<512, 512>>>();

    gather_out<<<(N_NODES * 512 / 4) / 256, 256>>>(out);
}

// round 12
// speedup vs baseline: 2.2543x; 1.0520x over previous
#include <cuda_runtime.h>
#include <cuda_fp16.h>
#include <cstdint>

#define N_NODES 4096
#define IN_FEAT 512
#define E3      1536
#define HEADS   8
#define HEAD_DIM 64
#define BAND    0.075f

// ---------------- scratch (static device globals: no allocation) ------------
__device__ float    g_xT[IN_FEAT * N_NODES];     // [k][m]
__device__ float    g_WT[IN_FEAT * 1024];        // [k][n]  n: Q(512)|K(512)
__device__ float    g_Qh[HEADS * N_NODES * 64];  // head-major [h][node][d]
__device__ float    g_Kh[HEADS * N_NODES * 64];
__device__ float    g_KhT[HEADS * 64 * N_NODES]; // [h][d][node]  (rescan)
__device__ __half   g_Kp16[HEADS * 64 * 4096];   // fragment-PAIRED fp16 tile images
__device__ __half   g_xAhi[512 * 4096];          // A-frag images of x (hi), per (nt,chunk)
__device__ __half   g_xAlo[512 * 4096];
__device__ __half   g_wBhi[64 * 4096];           // B-frag images of WV (hi), per (ct,chunk)
__device__ __half   g_wBlo[64 * 4096];
__device__ float    g_V[N_NODES * 512];          // node-major (written by v_mma)
__device__ unsigned g_adjbits[128 * N_NODES];    // [word][q]
__device__ int      g_argmax[HEADS * N_NODES];
__device__ int      g_fixcount;
__device__ int      g_fixlist[HEADS * N_NODES];

// ---------------- packed fp32x2 helpers (qkv gemm) ---------------------------
__device__ __forceinline__ unsigned long long pack2(float lo, float hi) {
    unsigned long long r;
    asm("mov.b64 %0, {%1, %2};" : "=l"(r) : "f"(lo), "f"(hi));
    return r;
}
__device__ __forceinline__ void unpack2(unsigned long long v, float& lo, float& hi) {
    asm("mov.b64 {%0, %1}, %2;" : "=f"(lo), "=f"(hi) : "l"(v));
}
__device__ __forceinline__ unsigned long long fma2(unsigned long long a,
                                                   unsigned long long b,
                                                   unsigned long long c) {
    unsigned long long d;
    asm("fma.rn.f32x2 %0, %1, %2, %3;" : "=l"(d) : "l"(a), "l"(b), "l"(c));
    return d;
}

// ---------------- mbarrier + bulk-copy helpers --------------------------------
__device__ __forceinline__ uint32_t smem_u32(const void* p) {
    uint32_t a;
    asm("{ .reg .u64 t; cvta.to.shared.u64 t, %1; cvt.u32.u64 %0, t; }"
        : "=r"(a) : "l"(p));
    return a;
}
__device__ __forceinline__ void mbar_init(uint32_t bar, uint32_t cnt) {
    asm volatile("mbarrier.init.shared.b64 [%0], %1;" :: "r"(bar), "r"(cnt) : "memory");
}
__device__ __forceinline__ void mbar_arrive_expect(uint32_t bar, uint32_t bytes) {
    asm volatile("mbarrier.arrive.expect_tx.shared.b64 _, [%0], %1;"
                 :: "r"(bar), "r"(bytes) : "memory");
}
__device__ __forceinline__ void bulk_g2s(uint32_t dst, const void* src,
                                         uint32_t bytes, uint32_t bar) {
    asm volatile(
        "cp.async.bulk.shared::cluster.global.mbarrier::complete_tx::bytes "
        "[%0], [%1], %2, [%3];"
        :: "r"(dst), "l"(src), "r"(bytes), "r"(bar) : "memory");
}
__device__ __forceinline__ void mbar_wait(uint32_t bar, uint32_t parity) {
    asm volatile(
        "{\n\t"
        ".reg .pred P;\n\t"
        "WL_%=:\n\t"
        "mbarrier.try_wait.parity.acquire.cta.shared::cta.b64 P, [%0], %1, 0x989680;\n\t"
        "@P bra WD_%=;\n\t"
        "bra WL_%=;\n\t"
        "WD_%=:\n\t"
        "}"
        :: "r"(bar), "r"(parity) : "memory");
}

// ---------------- fp16 MMA helpers --------------------------------------------
__device__ __forceinline__ uint32_t pack_h2(float x, float y) {
    __half2 v = __floats2half2_rn(x, y);
    return *reinterpret_cast<uint32_t*>(&v);
}
__device__ __forceinline__ void mma16(float* d, const uint32_t* a,
                                      uint32_t b0, uint32_t b1) {
    asm("mma.sync.aligned.m16n8k16.row.col.f32.f16.f16.f32 "
        "{%0,%1,%2,%3}, {%4,%5,%6,%7}, {%8,%9}, {%0,%1,%2,%3};"
        : "+f"(d[0]), "+f"(d[1]), "+f"(d[2]), "+f"(d[3])
        : "r"(a[0]), "r"(a[1]), "r"(a[2]), "r"(a[3]), "r"(b0), "r"(b1));
}
__device__ __forceinline__ float f16lo(float x) {
    return x - __half2float(__float2half_rn(x));
}

// ============================================================================
// prep: merged transposes (x, WQ, WK) + adj bitmask in ONE launch.
//   y < 128  : x transpose;  y < 160 : WQ/WK transpose;  y >= 160 : adj bits
// ============================================================================
__global__ __launch_bounds__(256) void prep(const float* __restrict__ x,
                                            const float* __restrict__ WQ,
                                            const float* __restrict__ WK,
                                            const int* __restrict__ adj) {
    __shared__ float t[32][33];
    const int txx = threadIdx.x, tyy = threadIdx.y;
    const int bx = blockIdx.x * 32;

    if (blockIdx.y < 128) {
        const int by = blockIdx.y * 32;
#pragma unroll
        for (int i = tyy; i < 32; i += 8)
            t[i][txx] = x[(size_t)(by + i) * IN_FEAT + bx + txx];
        __syncthreads();
#pragma unroll
        for (int i = tyy; i < 32; i += 8)
            g_xT[(size_t)(bx + i) * N_NODES + by + txx] = t[txx][i];
    } else if (blockIdx.y < 160) {
        const int yy = blockIdx.y - 128;
        const int wsel = yy >> 4;                 // 0..1
        const int by = (yy & 15) * 32;
        const float* W = (wsel == 0) ? WQ : WK;
#pragma unroll
        for (int i = tyy; i < 32; i += 8)
            t[i][txx] = W[(size_t)(by + i) * IN_FEAT + bx + txx];
        __syncthreads();
#pragma unroll
        for (int i = tyy; i < 32; i += 8)
            g_WT[(size_t)(bx + i) * 1024 + wsel * 512 + by + txx] = t[txx][i];
    } else {
        const int q = ((blockIdx.y - 160) * 16 + blockIdx.x) * 8 + tyy;
        const int* row = adj + (size_t)q * N_NODES;
#pragma unroll 4
        for (int w = 0; w < 128; w++) {
            unsigned m = __ballot_sync(0xffffffffu, row[w * 32 + txx] > 0);
            if (txx == 0) g_adjbits[w * N_NODES + q] = m;
        }
    }
}

// ============================================================================
// convert_v_operands: build fp16 hi/lo fragment images for the V projection.
//   blocks [0,512): A-images of x    (nt 0..63, chunk 0..7)
//   blocks [512,576): B-images of WV (ct 0..7,  chunk 0..7)
// A-image item (w,s,lane): mirrors score_mma's Q-fragment register layout.
// B-image item (nf,sp,lane): identical formula to the validated convert_k16.
// ============================================================================
__global__ __launch_bounds__(256) void convert_v_operands(
    const float* __restrict__ x, const float* __restrict__ WV) {
    const int b = blockIdx.x;
    if (b < 512) {
        const int nt = b >> 3, c = b & 7;
        __half2* dhi = (__half2*)(g_xAhi + (size_t)b * 4096);
        __half2* dlo = (__half2*)(g_xAlo + (size_t)b * 4096);
#pragma unroll
        for (int rep = 0; rep < 2; rep++) {
            const int it   = rep * 256 + threadIdx.x;   // 0..511
            const int w    = it >> 7;
            const int s    = (it >> 5) & 3;
            const int lane = it & 31;
            const int g    = lane >> 2, l4 = lane & 3;
            const int n0 = nt * 64 + w * 16 + g;
            const int n1 = n0 + 8;
            const int k0 = c * 64 + s * 16 + l4 * 2;
            const float* p0 = x + (size_t)n0 * 512 + k0;
            const float* p1 = x + (size_t)n1 * 512 + k0;
            float v[8] = {p0[0], p0[1], p1[0], p1[1], p0[8], p0[9], p1[8], p1[9]};
            dhi[it * 4 + 0] = __floats2half2_rn(v[0], v[1]);
            dhi[it * 4 + 1] = __floats2half2_rn(v[2], v[3]);
            dhi[it * 4 + 2] = __floats2half2_rn(v[4], v[5]);
            dhi[it * 4 + 3] = __floats2half2_rn(v[6], v[7]);
            dlo[it * 4 + 0] = __floats2half2_rn(f16lo(v[0]), f16lo(v[1]));
            dlo[it * 4 + 1] = __floats2half2_rn(f16lo(v[2]), f16lo(v[3]));
            dlo[it * 4 + 2] = __floats2half2_rn(f16lo(v[4]), f16lo(v[5]));
            dlo[it * 4 + 3] = __floats2half2_rn(f16lo(v[6]), f16lo(v[7]));
        }
    } else {
        const int b2 = b - 512;
        const int ct = b2 >> 3, c = b2 & 7;
        __half2* dhi = (__half2*)(g_wBhi + (size_t)b2 * 4096);
        __half2* dlo = (__half2*)(g_wBlo + (size_t)b2 * 4096);
#pragma unroll
        for (int rep = 0; rep < 2; rep++) {
            const int it   = rep * 256 + threadIdx.x;   // 0..511
            const int lane = it & 31;
            const int sp   = (it >> 5) & 1;
            const int nf   = it >> 6;
            const int key  = nf * 8 + (lane >> 2);
            const int kc   = sp * 32 + (lane & 3) * 2;
            const float* p = WV + (size_t)(ct * 64 + key) * 512 + c * 64 + kc;
            float v[8] = {p[0], p[1], p[8], p[9], p[16], p[17], p[24], p[25]};
            dhi[it * 4 + 0] = __floats2half2_rn(v[0], v[1]);
            dhi[it * 4 + 1] = __floats2half2_rn(v[2], v[3]);
            dhi[it * 4 + 2] = __floats2half2_rn(v[4], v[5]);
            dhi[it * 4 + 3] = __floats2half2_rn(v[6], v[7]);
            dlo[it * 4 + 0] = __floats2half2_rn(f16lo(v[0]), f16lo(v[1]));
            dlo[it * 4 + 1] = __floats2half2_rn(f16lo(v[2]), f16lo(v[3]));
            dlo[it * 4 + 2] = __floats2half2_rn(f16lo(v[4]), f16lo(v[5]));
            dlo[it * 4 + 3] = __floats2half2_rn(f16lo(v[6]), f16lo(v[7]));
        }
    }
}

// ============================================================================
// QK GEMM (fp32-exact) over n=1024 cols; K blocks also emit fp16 frag image.
// ============================================================================
#define QKV_KT 64
#define QKV_SMEM (4 * QKV_KT * 128 * 4)

__device__ __forceinline__ void qkv_issue(int t, int m0, int n0, int tid,
                                          float* As, float* Bs,
                                          uint32_t bar0, uint32_t bar1) {
    if (tid < 128) {
        const int buf = t & 1;
        const uint32_t bar = buf ? bar1 : bar0;
        mbar_arrive_expect(bar, 512);
        const int row = tid & 63;
        const int k   = t * QKV_KT + row;
        if (tid < 64) {
            bulk_g2s(smem_u32(&As[buf * QKV_KT * 128 + row * 128]),
                     &g_xT[(size_t)k * N_NODES + m0], 512, bar);
        } else {
            bulk_g2s(smem_u32(&Bs[buf * QKV_KT * 128 + row * 128]),
                     &g_WT[(size_t)k * 1024 + n0], 512, bar);
        }
    }
}

__global__ __launch_bounds__(512, 1) void qkv_gemm() {
    extern __shared__ float smem[];
    float* As = smem;
    float* Bs = smem + 2 * QKV_KT * 128;
    __shared__ __align__(8) unsigned long long mbar[2];

    const int tid = threadIdx.x;
    const int tx  = tid & 31;
    const int ty  = tid >> 5;
    const int n0  = blockIdx.x * 128;     // 0..896
    const int m0  = blockIdx.y * 128;
    const uint32_t bar0 = smem_u32(&mbar[0]);
    const uint32_t bar1 = smem_u32(&mbar[1]);

    if (blockIdx.x == 0 && blockIdx.y == 0 && tid == 0) g_fixcount = 0;

    if (tid == 0) { mbar_init(bar0, 128); mbar_init(bar1, 128); }
    __syncthreads();

    qkv_issue(0, m0, n0, tid, As, Bs, bar0, bar1);
    qkv_issue(1, m0, n0, tid, As, Bs, bar0, bar1);

    unsigned long long c[4][4];
#pragma unroll
    for (int i = 0; i < 4; i++)
#pragma unroll
        for (int j = 0; j < 4; j++) c[i][j] = 0ULL;

    const int ntiles = IN_FEAT / QKV_KT;
    for (int t = 0; t < ntiles; t++) {
        const int buf = t & 1;
        mbar_wait(buf ? bar1 : bar0, (t >> 1) & 1);
        const float* a = As + buf * QKV_KT * 128;
        const float* b = Bs + buf * QKV_KT * 128;
#pragma unroll 8
        for (int k = 0; k < QKV_KT; k++) {
            const ulonglong2* ap = (const ulonglong2*)&a[k * 128 + ty * 8];
            ulonglong2 a01 = ap[0];
            ulonglong2 a23 = ap[1];
            float4 bv = *(const float4*)&b[k * 128 + tx * 4];
            unsigned long long bd[4];
            bd[0] = pack2(bv.x, bv.x);
            bd[1] = pack2(bv.y, bv.y);
            bd[2] = pack2(bv.z, bv.z);
            bd[3] = pack2(bv.w, bv.w);
#pragma unroll
            for (int j = 0; j < 4; j++) {
                c[0][j] = fma2(a01.x, bd[j], c[0][j]);
                c[1][j] = fma2(a01.y, bd[j], c[1][j]);
                c[2][j] = fma2(a23.x, bd[j], c[2][j]);
                c[3][j] = fma2(a23.y, bd[j], c[3][j]);
            }
        }
        __syncthreads();
        if (t + 2 < ntiles) qkv_issue(t + 2, m0, n0, tid, As, Bs, bar0, bar1);
    }

    const int col = (n0 & 511) + tx * 4;
    const bool isK = (n0 >= 512);
    float* pb = (isK ? g_Kh : g_Qh) + (size_t)(col >> 6) * (N_NODES * 64) + (col & 63);

    const int hh = col >> 6;
    const int d0 = col & 63;
    const int sp = d0 >> 5;
    const int jj = (d0 & 31) >> 3;
    const int lp = (d0 & 7) >> 1;

#pragma unroll
    for (int mp = 0; mp < 4; mp++) {
        float lo0, hi0, lo1, hi1, lo2, hi2, lo3, hi3;
        unpack2(c[mp][0], lo0, hi0);
        unpack2(c[mp][1], lo1, hi1);
        unpack2(c[mp][2], lo2, hi2);
        unpack2(c[mp][3], lo3, hi3);
        const int row0 = m0 + ty * 8 + mp * 2;
        *(float4*)&pb[(size_t)row0 * 64]       = make_float4(lo0, lo1, lo2, lo3);
        *(float4*)&pb[(size_t)(row0 + 1) * 64] = make_float4(hi0, hi1, hi2, hi3);

        if (isK) {
#pragma unroll
            for (int r = 0; r < 2; r++) {
                const int node = row0 + r;
                const int kk = node & 63;
                const int kt = node >> 6;
                __half2* dst = (__half2*)(g_Kp16 + (size_t)(hh * 64 + kt) * 4096);
                const int lane = ((kk & 7) << 2) | lp;
                const int idx  = (((kk >> 3) * 2 + sp) * 32 + lane) * 4 + jj;
                if (r == 0) {
                    dst[idx]     = __floats2half2_rn(lo0, lo1);
                    dst[idx + 4] = __floats2half2_rn(lo2, lo3);
                } else {
                    dst[idx]     = __floats2half2_rn(hi0, hi1);
                    dst[idx + 4] = __floats2half2_rn(hi2, hi3);
                }
            }
        }
    }
}

// ============================================================================
// v_mma: V = x @ WV^T via 3-chain split-fp16 MMA (hh + lo*hi + hi*lo).
// Block = (node-tile 64, col-tile 64); 128 threads; 2-deep operand ring.
// ============================================================================
#define VM_SMEM (2 * 4 * 8192)   // 2 slots x {Ahi,Alo,Bhi,Blo} x 8KB = 64 KB

__global__ __launch_bounds__(128, 1) void v_mma() {
    extern __shared__ __half vsm[];   // [2][4][4096]
    __shared__ __align__(8) unsigned long long s_bar[2];

    const int tid  = threadIdx.x;
    const int w    = tid >> 5;
    const int lane = tid & 31;
    const int g    = lane >> 2;
    const int l4   = lane & 3;
    const int nt   = blockIdx.x;
    const int ct   = blockIdx.y;

    const uint32_t bar0 = smem_u32(&s_bar[0]);
    const uint32_t bar1 = smem_u32(&s_bar[1]);
    if (tid == 0) { mbar_init(bar0, 1); mbar_init(bar1, 1); }
    __syncthreads();

    auto issue = [&](int c) {
        const int slot = c & 1;
        const uint32_t bar = slot ? bar1 : bar0;
        __half* base = vsm + (size_t)slot * 4 * 4096;
        mbar_arrive_expect(bar, 32768);
        bulk_g2s(smem_u32(base),            g_xAhi + (size_t)(nt * 8 + c) * 4096, 8192, bar);
        bulk_g2s(smem_u32(base + 4096),     g_xAlo + (size_t)(nt * 8 + c) * 4096, 8192, bar);
        bulk_g2s(smem_u32(base + 2 * 4096), g_wBhi + (size_t)(ct * 8 + c) * 4096, 8192, bar);
        bulk_g2s(smem_u32(base + 3 * 4096), g_wBlo + (size_t)(ct * 8 + c) * 4096, 8192, bar);
    };
    if (tid == 0) { issue(0); issue(1); }

    float acc[8][4];
#pragma unroll
    for (int nf = 0; nf < 8; nf++)
#pragma unroll
        for (int j = 0; j < 4; j++) acc[nf][j] = 0.f;

    for (int c = 0; c < 8; c++) {
        const int slot = c & 1;
        mbar_wait(slot ? bar1 : bar0, (c >> 1) & 1);
        const __half* Ah = vsm + (size_t)slot * 4 * 4096;
        const __half* Al = Ah + 4096;
        const __half* Bh = Ah + 2 * 4096;
        const __half* Bl = Ah + 3 * 4096;

        uint32_t ah[4][4], al[4][4];
#pragma unroll
        for (int s = 0; s < 4; s++) {
            const uint4 vh = *(const uint4*)&Ah[((w * 4 + s) * 32 + lane) * 8];
            ah[s][0] = vh.x; ah[s][1] = vh.y; ah[s][2] = vh.z; ah[s][3] = vh.w;
            const uint4 vl = *(const uint4*)&Al[((w * 4 + s) * 32 + lane) * 8];
            al[s][0] = vl.x; al[s][1] = vl.y; al[s][2] = vl.z; al[s][3] = vl.w;
        }

#pragma unroll
        for (int nf = 0; nf < 8; nf++) {
#pragma unroll
            for (int sp = 0; sp < 2; sp++) {
                const uint4 bh = *(const uint4*)&Bh[(size_t)(((nf * 2 + sp) * 32 + lane)) * 8];
                const uint4 bl = *(const uint4*)&Bl[(size_t)(((nf * 2 + sp) * 32 + lane)) * 8];
                mma16(acc[nf], ah[2 * sp],     bh.x, bh.y);
                mma16(acc[nf], ah[2 * sp + 1], bh.z, bh.w);
                mma16(acc[nf], al[2 * sp],     bh.x, bh.y);
                mma16(acc[nf], al[2 * sp + 1], bh.z, bh.w);
                mma16(acc[nf], ah[2 * sp],     bl.x, bl.y);
                mma16(acc[nf], ah[2 * sp + 1], bl.z, bl.w);
            }
        }
        __syncthreads();
        if (tid == 0 && c + 2 < 8) issue(c + 2);
    }

    const int n0 = nt * 64 + w * 16 + g;
    const int n1 = n0 + 8;
#pragma unroll
    for (int nf = 0; nf < 8; nf++) {
        const int colv = ct * 64 + nf * 8 + l4 * 2;
        *(float2*)&g_V[(size_t)n0 * 512 + colv] = make_float2(acc[nf][0], acc[nf][1]);
        *(float2*)&g_V[(size_t)n1 * 512 + colv] = make_float2(acc[nf][2], acc[nf][3]);
    }
}

// ============================================================================
// K transpose for rescan:  g_Kh[h][node][d] -> g_KhT[h][d][node]
// ============================================================================
__global__ __launch_bounds__(256) void transpose_k() {
    __shared__ float t[32][33];
    const int h  = blockIdx.z;
    const int d0 = blockIdx.y * 32;
    const int n0 = blockIdx.x * 32;
    const int txx = threadIdx.x, tyy = threadIdx.y;
    const float* src = g_Kh + (size_t)h * N_NODES * 64;
#pragma unroll
    for (int i = tyy; i < 32; i += 8)
        t[i][txx] = src[(size_t)(n0 + i) * 64 + d0 + txx];
    __syncthreads();
    float* dst = g_KhT + (size_t)h * 64 * N_NODES;
#pragma unroll
    for (int i = tyy; i < 32; i += 8)
        dst[(size_t)(d0 + i) * N_NODES + n0 + txx] = t[txx][i];
}

// ============================================================================
// rare index recovery (validated)
// ============================================================================
__device__ __forceinline__ void rare2(const float (&acc)[8][4], int cofs,
                                      int t, int l4, float tmax,
                                      float& best, float& best2, int& bk) {
    float sec = -3e38f;
    int   idx = bk;
    bool  taken = false;
#pragma unroll
    for (int nf = 0; nf < 8; nf++)
#pragma unroll
        for (int c = 0; c < 2; c++) {
            const float v = acc[nf][cofs + c];
            if (v == tmax && !taken) {
                taken = true;
                idx = t * 64 + nf * 8 + l4 * 2 + c;
            } else {
                sec = fmaxf(sec, v);
            }
        }
    best2 = fmaxf(best2, fmaxf(best, sec));
    best  = tmax;
    bk    = idx;
}

// ============================================================================
// Score argmax via mma.sync m16n8k16.f16; mask words PREFETCHED 1 tile ahead.
// ============================================================================
__global__ __launch_bounds__(128, 4) void score_mma() {
    __shared__ __align__(16) __half sK[4][4096];
    __shared__ __align__(8) unsigned long long s_bar[4];

    const int tid  = threadIdx.x;
    const int w    = tid >> 5;
    const int lane = tid & 31;
    const int g    = lane >> 2;
    const int l4   = lane & 3;
    const int h    = blockIdx.y;
    const int qt   = blockIdx.x;
    const int qA   = qt * 64 + w * 16 + g;
    const int qB   = qA + 8;

    uint32_t bar[4];
#pragma unroll
    for (int i = 0; i < 4; i++) bar[i] = smem_u32(&s_bar[i]);
    const __half* Ksrc = g_Kp16 + (size_t)h * 64 * 4096;

    if (tid == 0) {
#pragma unroll
        for (int i = 0; i < 4; i++) mbar_init(bar[i], 1);
    }
    __syncthreads();

    if (tid == 0) {
#pragma unroll
        for (int i = 0; i < 4; i++) {
            mbar_arrive_expect(bar[i], 8192);
            bulk_g2s(smem_u32(&sK[i][0]), Ksrc + (size_t)i * 4096, 8192, bar[i]);
        }
    }

    uint32_t a[4][4];
    {
        const float* QA = g_Qh + ((size_t)h * N_NODES + qA) * 64;
        const float* QB = QA + 8 * 64;
#pragma unroll
        for (int s = 0; s < 4; s++) {
            const int c = s * 16 + 2 * l4;
            a[s][0] = pack_h2(QA[c],     QA[c + 1]);
            a[s][1] = pack_h2(QB[c],     QB[c + 1]);
            a[s][2] = pack_h2(QA[c + 8], QA[c + 9]);
            a[s][3] = pack_h2(QB[c + 8], QB[c + 9]);
        }
    }

    float bestA = -3.3e38f, best2A = -3.3e38f;
    float bestB = -3.3e38f, best2B = -3.3e38f;
    int   bkA = 0, bkB = 0;

    // mask words for tile 0 (prefetched)
    unsigned cw0A = g_adjbits[0 * N_NODES + qA];
    unsigned cw1A = g_adjbits[1 * N_NODES + qA];
    unsigned cw0B = g_adjbits[0 * N_NODES + qB];
    unsigned cw1B = g_adjbits[1 * N_NODES + qB];

    for (int t = 0; t < 64; t++) {
        const int buf = t & 3;
        const int ph  = (t >> 2) & 1;

        // acc init from current (already-resident) mask words
        float acc[8][4];
#pragma unroll
        for (int nf = 0; nf < 8; nf++) {
            const unsigned wdA = (nf < 4) ? cw0A : cw1A;
            const unsigned wdB = (nf < 4) ? cw0B : cw1B;
            const int sh = (nf & 3) * 8 + l4 * 2;
            acc[nf][0] = ((wdA >> sh) & 1u)       ? 0.0f : -3e38f;
            acc[nf][1] = ((wdA >> (sh + 1)) & 1u) ? 0.0f : -3e38f;
            acc[nf][2] = ((wdB >> sh) & 1u)       ? 0.0f : -3e38f;
            acc[nf][3] = ((wdB >> (sh + 1)) & 1u) ? 0.0f : -3e38f;
        }
        // prefetch next tile's words (latency hidden under MMA)
        if (t + 1 < 64) {
            cw0A = g_adjbits[(size_t)(2 * t + 2) * N_NODES + qA];
            cw1A = g_adjbits[(size_t)(2 * t + 3) * N_NODES + qA];
            cw0B = g_adjbits[(size_t)(2 * t + 2) * N_NODES + qB];
            cw1B = g_adjbits[(size_t)(2 * t + 3) * N_NODES + qB];
        }

        mbar_wait(bar[buf], ph);
        const __half* kb = &sK[buf][0];
#pragma unroll
        for (int nf = 0; nf < 8; nf++) {
#pragma unroll
            for (int sp = 0; sp < 2; sp++) {
                const uint4 bb = *(const uint4*)&kb[(size_t)(((nf * 2 + sp) * 32 + lane)) * 8];
                mma16(acc[nf], a[2 * sp],     bb.x, bb.y);
                mma16(acc[nf], a[2 * sp + 1], bb.z, bb.w);
            }
        }
        __syncthreads();
        if (tid == 0 && t + 4 < 64) {
            mbar_arrive_expect(bar[buf], 8192);
            bulk_g2s(smem_u32(&sK[buf][0]), Ksrc + (size_t)(t + 4) * 4096, 8192, bar[buf]);
        }

        float tA = fmaxf(acc[0][0], acc[0][1]);
        float tB = fmaxf(acc[0][2], acc[0][3]);
#pragma unroll
        for (int nf = 1; nf < 8; nf++) {
            tA = fmaxf(tA, fmaxf(acc[nf][0], acc[nf][1]));
            tB = fmaxf(tB, fmaxf(acc[nf][2], acc[nf][3]));
        }
        if (tA > bestA) rare2(acc, 0, t, l4, tA, bestA, best2A, bkA);
        else            best2A = fmaxf(best2A, tA);
        if (tB > bestB) rare2(acc, 2, t, l4, tB, bestB, best2B, bkB);
        else            best2B = fmaxf(best2B, tB);
    }

#pragma unroll
    for (int off = 1; off < 4; off <<= 1) {
        float ob  = __shfl_xor_sync(0xffffffffu, bestA, off);
        int   obk = __shfl_xor_sync(0xffffffffu, bkA,  off);
        float ob2 = __shfl_xor_sync(0xffffffffu, best2A, off);
        best2A = fmaxf(fmaxf(best2A, ob2), fminf(bestA, ob));
        if (ob > bestA || (ob == bestA && obk < bkA)) { bestA = ob; bkA = obk; }

        ob  = __shfl_xor_sync(0xffffffffu, bestB, off);
        obk = __shfl_xor_sync(0xffffffffu, bkB,  off);
        ob2 = __shfl_xor_sync(0xffffffffu, best2B, off);
        best2B = fmaxf(fmaxf(best2B, ob2), fminf(bestB, ob));
        if (ob > bestB || (ob == bestB && obk < bkB)) { bestB = ob; bkB = obk; }
    }

    if (l4 == 0) {
        const int hqA = h * N_NODES + qA;
        const int hqB = h * N_NODES + qB;
        g_argmax[hqA] = bkA;
        g_argmax[hqB] = bkB;
        if (bestA - best2A < BAND) g_fixlist[atomicAdd(&g_fixcount, 1)] = hqA;
        if (bestB - best2B < BAND) g_fixlist[atomicAdd(&g_fixcount, 1)] = hqB;
    }
}

// ============================================================================
// Pass 2: exact fp32 re-argmax of flagged rows — coalesced via K^T.
// ============================================================================
__global__ __launch_bounds__(512) void rescan() {
    __shared__ float sq[64];
    __shared__ float s_best[16];
    __shared__ int   s_bk[16];
    const int nfix = g_fixcount;
    const int tid = threadIdx.x, lane = tid & 31, wrp = tid >> 5;

    for (int i = blockIdx.x; i < nfix; i += gridDim.x) {
        const int hq = g_fixlist[i];
        const int h = hq >> 12, q = hq & (N_NODES - 1);
        if (tid < 64) sq[tid] = g_Qh[((size_t)h * N_NODES + q) * 64 + tid];
        __syncthreads();

        const float4* KT = (const float4*)(g_KhT + (size_t)h * 64 * N_NODES);
        float acc[8] = {0.f, 0.f, 0.f, 0.f, 0.f, 0.f, 0.f, 0.f};
#pragma unroll 4
        for (int d = 0; d < 64; d++) {
            const float qd = sq[d];
            const float4 v0 = KT[(size_t)d * 1024 + tid];
            const float4 v1 = KT[(size_t)d * 1024 + 512 + tid];
            acc[0] += qd * v0.x; acc[1] += qd * v0.y;
            acc[2] += qd * v0.z; acc[3] += qd * v0.w;
            acc[4] += qd * v1.x; acc[5] += qd * v1.y;
            acc[6] += qd * v1.z; acc[7] += qd * v1.w;
        }

        const int k0 = tid * 4, k1 = 2048 + tid * 4;
        const unsigned w0 = g_adjbits[(size_t)(k0 >> 5) * N_NODES + q];
        const unsigned w1 = g_adjbits[(size_t)(k1 >> 5) * N_NODES + q];
        float best = -3e38f;
        int   bk   = 1 << 30;
#pragma unroll
        for (int j = 0; j < 4; j++) {
            if ((w0 >> ((k0 + j) & 31)) & 1u)
                if (acc[j] > best) { best = acc[j]; bk = k0 + j; }
        }
#pragma unroll
        for (int j = 0; j < 4; j++) {
            if ((w1 >> ((k1 + j) & 31)) & 1u)
                if (acc[4 + j] > best) { best = acc[4 + j]; bk = k1 + j; }
        }
#pragma unroll
        for (int off = 16; off > 0; off >>= 1) {
            float ob  = __shfl_xor_sync(0xffffffffu, best, off);
            int   obk = __shfl_xor_sync(0xffffffffu, bk, off);
            if (ob > best || (ob == best && obk < bk)) { best = ob; bk = obk; }
        }
        if (lane == 0) { s_best[wrp] = best; s_bk[wrp] = bk; }
        __syncthreads();
        if (tid == 0) {
            float b = s_best[0]; int k = s_bk[0];
#pragma unroll
            for (int j = 1; j < 16; j++)
                if (s_best[j] > b || (s_best[j] == b && s_bk[j] < k)) {
                    b = s_best[j]; k = s_bk[j];
                }
            g_argmax[hq] = k;
        }
        __syncthreads();
    }
}

// ============================================================================
// out[q, h*64+d] = V[argmax(h,q), h*64+d] / HEADS
// ============================================================================
__global__ __launch_bounds__(256) void gather_out(float* __restrict__ out) {
    const int idx = blockIdx.x * blockDim.x + threadIdx.x;
    const int q   = idx >> 7;
    const int c4  = idx & 127;
    const int h   = c4 >> 4;
    const int k   = g_argmax[h * N_NODES + q];
    float4 t = *(const float4*)&g_V[(size_t)k * 512 + c4 * 4];
    float4 v = make_float4(t.x * 0.125f, t.y * 0.125f, t.z * 0.125f, t.w * 0.125f);
    *(float4*)&out[(size_t)idx * 4] = v;
}

// ============================================================================
extern "C" void kernel_launch(void* const* d_in, const int* in_sizes, int n_in,
                              void* d_out, int out_size)
{
    const float* x   = (const float*)d_in[0];
    const int*   adj = (const int*)d_in[1];
    const float* WQ  = (const float*)d_in[2];
    const float* WK  = (const float*)d_in[3];
    const float* WV  = (const float*)d_in[4];
    float* out = (float*)d_out;

    cudaFuncSetAttribute(qkv_gemm,
                         cudaFuncAttributeMaxDynamicSharedMemorySize, QKV_SMEM);
    cudaFuncSetAttribute(v_mma,
                         cudaFuncAttributeMaxDynamicSharedMemorySize, VM_SMEM);

    dim3 tb(32, 8);
    convert_v_operands<<<576, 256>>>(x, WV);
    prep<<<dim3(16, 192), tb>>>(x, WQ, WK, adj);

    qkv_gemm<<<dim3(1024 / 128, N_NODES / 128), 512, QKV_SMEM>>>();

    v_mma<<<dim3(64, 8), 128, VM_SMEM>>>();

    transpose_k<<<dim3(N_NODES / 32, 2, HEADS), tb>>>();

    score_mma<<<dim3(N_NODES / 64, HEADS), 128>>>();

    rescan<<<512, 512>>>();

    gather_out<<<(N_NODES * 512 / 4) / 256, 256>>>(out);
}

// round 13
// speedup vs baseline: 2.9816x; 1.3226x over previous
#include <cuda_runtime.h>
#include <cuda_fp16.h>
#include <cstdint>

#define N_NODES 4096
#define IN_FEAT 512
#define HEADS   8
#define HEAD_DIM 64
#define BAND    0.075f

// ---------------- scratch (static device globals: no allocation) ------------
__device__ float    g_Qh[HEADS * N_NODES * 64];  // head-major [h][node][d]
__device__ float    g_Kh[HEADS * N_NODES * 64];
__device__ float    g_KhT[HEADS * 64 * N_NODES]; // [h][d][node]  (rescan)
__device__ __half   g_Kp16[HEADS * 64 * 4096];   // fragment-PAIRED fp16 tile images
__device__ __half   g_xAhi[512 * 4096];          // A-frag images of x (hi), (nt,chunk)
__device__ __half   g_xAlo[512 * 4096];
__device__ __half   g_wBhi[3 * 64 * 4096];       // B-frag images of WQ|WK|WV (hi)
__device__ __half   g_wBlo[3 * 64 * 4096];
__device__ float    g_V[N_NODES * 512];          // node-major
__device__ unsigned g_adjbits[128 * N_NODES];    // [word][q]
__device__ int      g_argmax[HEADS * N_NODES];
__device__ int      g_fixcount;
__device__ int      g_fixlist[HEADS * N_NODES];

// ---------------- mbarrier + bulk-copy helpers --------------------------------
__device__ __forceinline__ uint32_t smem_u32(const void* p) {
    uint32_t a;
    asm("{ .reg .u64 t; cvta.to.shared.u64 t, %1; cvt.u32.u64 %0, t; }"
        : "=r"(a) : "l"(p));
    return a;
}
__device__ __forceinline__ void mbar_init(uint32_t bar, uint32_t cnt) {
    asm volatile("mbarrier.init.shared.b64 [%0], %1;" :: "r"(bar), "r"(cnt) : "memory");
}
__device__ __forceinline__ void mbar_arrive_expect(uint32_t bar, uint32_t bytes) {
    asm volatile("mbarrier.arrive.expect_tx.shared.b64 _, [%0], %1;"
                 :: "r"(bar), "r"(bytes) : "memory");
}
__device__ __forceinline__ void bulk_g2s(uint32_t dst, const void* src,
                                         uint32_t bytes, uint32_t bar) {
    asm volatile(
        "cp.async.bulk.shared::cluster.global.mbarrier::complete_tx::bytes "
        "[%0], [%1], %2, [%3];"
        :: "r"(dst), "l"(src), "r"(bytes), "r"(bar) : "memory");
}
__device__ __forceinline__ void mbar_wait(uint32_t bar, uint32_t parity) {
    asm volatile(
        "{\n\t"
        ".reg .pred P;\n\t"
        "WL_%=:\n\t"
        "mbarrier.try_wait.parity.acquire.cta.shared::cta.b64 P, [%0], %1, 0x989680;\n\t"
        "@P bra WD_%=;\n\t"
        "bra WL_%=;\n\t"
        "WD_%=:\n\t"
        "}"
        :: "r"(bar), "r"(parity) : "memory");
}

// ---------------- fp16 MMA helpers --------------------------------------------
__device__ __forceinline__ uint32_t pack_h2(float x, float y) {
    __half2 v = __floats2half2_rn(x, y);
    return *reinterpret_cast<uint32_t*>(&v);
}
__device__ __forceinline__ void mma16(float* d, const uint32_t* a,
                                      uint32_t b0, uint32_t b1) {
    asm("mma.sync.aligned.m16n8k16.row.col.f32.f16.f16.f32 "
        "{%0,%1,%2,%3}, {%4,%5,%6,%7}, {%8,%9}, {%0,%1,%2,%3};"
        : "+f"(d[0]), "+f"(d[1]), "+f"(d[2]), "+f"(d[3])
        : "r"(a[0]), "r"(a[1]), "r"(a[2]), "r"(a[3]), "r"(b0), "r"(b1));
}
__device__ __forceinline__ float f16lo(float x) {
    return x - __half2float(__float2half_rn(x));
}

// ============================================================================
// prep_all: ONE launch.
//   b < 512        : A-frag hi/lo images of x      (nt = b>>3, chunk = b&7)
//   b < 704        : B-frag hi/lo images of W      (wsel = (b-512)/64, ...)
//   b < 1216       : adj -> bitmask (8 q rows per block)
// ============================================================================
__global__ __launch_bounds__(256) void prep_all(const float* __restrict__ x,
                                                const float* __restrict__ WQ,
                                                const float* __restrict__ WK,
                                                const float* __restrict__ WV,
                                                const int* __restrict__ adj) {
    const int b = blockIdx.x;
    if (b == 0 && threadIdx.x == 0) g_fixcount = 0;

    if (b < 512) {
        const int nt = b >> 3, c = b & 7;
        __half2* dhi = (__half2*)(g_xAhi + (size_t)b * 4096);
        __half2* dlo = (__half2*)(g_xAlo + (size_t)b * 4096);
#pragma unroll
        for (int rep = 0; rep < 2; rep++) {
            const int it   = rep * 256 + threadIdx.x;   // 0..511
            const int w    = it >> 7;
            const int s    = (it >> 5) & 3;
            const int lane = it & 31;
            const int g    = lane >> 2, l4 = lane & 3;
            const int n0 = nt * 64 + w * 16 + g;
            const int n1 = n0 + 8;
            const int k0 = c * 64 + s * 16 + l4 * 2;
            const float* p0 = x + (size_t)n0 * 512 + k0;
            const float* p1 = x + (size_t)n1 * 512 + k0;
            float v[8] = {p0[0], p0[1], p1[0], p1[1], p0[8], p0[9], p1[8], p1[9]};
            dhi[it * 4 + 0] = __floats2half2_rn(v[0], v[1]);
            dhi[it * 4 + 1] = __floats2half2_rn(v[2], v[3]);
            dhi[it * 4 + 2] = __floats2half2_rn(v[4], v[5]);
            dhi[it * 4 + 3] = __floats2half2_rn(v[6], v[7]);
            dlo[it * 4 + 0] = __floats2half2_rn(f16lo(v[0]), f16lo(v[1]));
            dlo[it * 4 + 1] = __floats2half2_rn(f16lo(v[2]), f16lo(v[3]));
            dlo[it * 4 + 2] = __floats2half2_rn(f16lo(v[4]), f16lo(v[5]));
            dlo[it * 4 + 3] = __floats2half2_rn(f16lo(v[6]), f16lo(v[7]));
        }
    } else if (b < 704) {
        const int b2 = b - 512;                 // 0..191
        const int wsel = b2 >> 6;               // 0=Q,1=K,2=V
        const int r  = b2 & 63;
        const int ct = r >> 3, c = r & 7;
        const float* W = (wsel == 0) ? WQ : ((wsel == 1) ? WK : WV);
        __half2* dhi = (__half2*)(g_wBhi + (size_t)b2 * 4096);
        __half2* dlo = (__half2*)(g_wBlo + (size_t)b2 * 4096);
#pragma unroll
        for (int rep = 0; rep < 2; rep++) {
            const int it   = rep * 256 + threadIdx.x;   // 0..511
            const int lane = it & 31;
            const int sp   = (it >> 5) & 1;
            const int nf   = it >> 6;
            const int key  = nf * 8 + (lane >> 2);
            const int kc   = sp * 32 + (lane & 3) * 2;
            const float* p = W + (size_t)(ct * 64 + key) * 512 + c * 64 + kc;
            float v[8] = {p[0], p[1], p[8], p[9], p[16], p[17], p[24], p[25]};
            dhi[it * 4 + 0] = __floats2half2_rn(v[0], v[1]);
            dhi[it * 4 + 1] = __floats2half2_rn(v[2], v[3]);
            dhi[it * 4 + 2] = __floats2half2_rn(v[4], v[5]);
            dhi[it * 4 + 3] = __floats2half2_rn(v[6], v[7]);
            dlo[it * 4 + 0] = __floats2half2_rn(f16lo(v[0]), f16lo(v[1]));
            dlo[it * 4 + 1] = __floats2half2_rn(f16lo(v[2]), f16lo(v[3]));
            dlo[it * 4 + 2] = __floats2half2_rn(f16lo(v[4]), f16lo(v[5]));
            dlo[it * 4 + 3] = __floats2half2_rn(f16lo(v[6]), f16lo(v[7]));
        }
    } else {
        const int q = (b - 704) * 8 + (threadIdx.x >> 5);
        const int lane = threadIdx.x & 31;
        const int* row = adj + (size_t)q * N_NODES;
#pragma unroll 4
        for (int w = 0; w < 128; w++) {
            unsigned m = __ballot_sync(0xffffffffu, row[w * 32 + lane] > 0);
            if (lane == 0) g_adjbits[w * N_NODES + q] = m;
        }
    }
}

// ============================================================================
// proj_mma: Q|K|V = x @ W^T via 3-chain split-fp16 MMA (hh + lo*hi + hi*lo).
// Grid (nt 64, ct 24): ct 0-7 -> Q, 8-15 -> K (+Kp16 image), 16-23 -> V.
// Block 128 threads; 2-deep operand ring (64 KB smem).
// ============================================================================
#define VM_SMEM (2 * 4 * 8192)

__global__ __launch_bounds__(128, 1) void proj_mma() {
    extern __shared__ __half vsm[];   // [2][4][4096]
    __shared__ __align__(8) unsigned long long s_bar[2];

    const int tid  = threadIdx.x;
    const int w    = tid >> 5;
    const int lane = tid & 31;
    const int g    = lane >> 2;
    const int l4   = lane & 3;
    const int nt   = blockIdx.x;
    const int ct   = blockIdx.y;
    const int wsel = ct >> 3;          // 0=Q, 1=K, 2=V
    const int ct8  = ct & 7;

    const uint32_t bar0 = smem_u32(&s_bar[0]);
    const uint32_t bar1 = smem_u32(&s_bar[1]);
    if (tid == 0) { mbar_init(bar0, 1); mbar_init(bar1, 1); }
    __syncthreads();

    auto issue = [&](int c) {
        const int slot = c & 1;
        const uint32_t bar = slot ? bar1 : bar0;
        __half* base = vsm + (size_t)slot * 4 * 4096;
        const size_t bi = (size_t)((wsel * 8 + ct8) * 8 + c) * 4096;
        mbar_arrive_expect(bar, 32768);
        bulk_g2s(smem_u32(base),            g_xAhi + (size_t)(nt * 8 + c) * 4096, 8192, bar);
        bulk_g2s(smem_u32(base + 4096),     g_xAlo + (size_t)(nt * 8 + c) * 4096, 8192, bar);
        bulk_g2s(smem_u32(base + 2 * 4096), g_wBhi + bi, 8192, bar);
        bulk_g2s(smem_u32(base + 3 * 4096), g_wBlo + bi, 8192, bar);
    };
    if (tid == 0) { issue(0); issue(1); }

    float acc[8][4];
#pragma unroll
    for (int nf = 0; nf < 8; nf++)
#pragma unroll
        for (int j = 0; j < 4; j++) acc[nf][j] = 0.f;

    for (int c = 0; c < 8; c++) {
        const int slot = c & 1;
        mbar_wait(slot ? bar1 : bar0, (c >> 1) & 1);
        const __half* Ah = vsm + (size_t)slot * 4 * 4096;
        const __half* Al = Ah + 4096;
        const __half* Bh = Ah + 2 * 4096;
        const __half* Bl = Ah + 3 * 4096;

        uint32_t ah[4][4], al[4][4];
#pragma unroll
        for (int s = 0; s < 4; s++) {
            const uint4 vh = *(const uint4*)&Ah[((w * 4 + s) * 32 + lane) * 8];
            ah[s][0] = vh.x; ah[s][1] = vh.y; ah[s][2] = vh.z; ah[s][3] = vh.w;
            const uint4 vl = *(const uint4*)&Al[((w * 4 + s) * 32 + lane) * 8];
            al[s][0] = vl.x; al[s][1] = vl.y; al[s][2] = vl.z; al[s][3] = vl.w;
        }

#pragma unroll
        for (int nf = 0; nf < 8; nf++) {
#pragma unroll
            for (int sp = 0; sp < 2; sp++) {
                const uint4 bh = *(const uint4*)&Bh[(size_t)(((nf * 2 + sp) * 32 + lane)) * 8];
                const uint4 bl = *(const uint4*)&Bl[(size_t)(((nf * 2 + sp) * 32 + lane)) * 8];
                mma16(acc[nf], ah[2 * sp],     bh.x, bh.y);
                mma16(acc[nf], ah[2 * sp + 1], bh.z, bh.w);
                mma16(acc[nf], al[2 * sp],     bh.x, bh.y);
                mma16(acc[nf], al[2 * sp + 1], bh.z, bh.w);
                mma16(acc[nf], ah[2 * sp],     bl.x, bl.y);
                mma16(acc[nf], ah[2 * sp + 1], bl.z, bl.w);
            }
        }
        __syncthreads();
        if (tid == 0 && c + 2 < 8) issue(c + 2);
    }

    const int n0 = nt * 64 + w * 16 + g;
    const int n1 = n0 + 8;

    if (wsel == 2) {
        // V: node-major [node][512]
#pragma unroll
        for (int nf = 0; nf < 8; nf++) {
            const int colv = ct8 * 64 + nf * 8 + l4 * 2;
            *(float2*)&g_V[(size_t)n0 * 512 + colv] = make_float2(acc[nf][0], acc[nf][1]);
            *(float2*)&g_V[(size_t)n1 * 512 + colv] = make_float2(acc[nf][2], acc[nf][3]);
        }
    } else {
        // Q/K: head-major [h=ct8][node][d]
        float* dst = ((wsel == 0) ? g_Qh : g_Kh) + (size_t)ct8 * N_NODES * 64;
#pragma unroll
        for (int nf = 0; nf < 8; nf++) {
            const int d = nf * 8 + l4 * 2;
            *(float2*)&dst[(size_t)n0 * 64 + d] = make_float2(acc[nf][0], acc[nf][1]);
            *(float2*)&dst[(size_t)n1 * 64 + d] = make_float2(acc[nf][2], acc[nf][3]);
        }
        if (wsel == 1) {
            // Kp16 fragment image (validated convert_k16 formula)
            __half2* img = (__half2*)(g_Kp16 + (size_t)(ct8 * 64 + nt) * 4096);
#pragma unroll
            for (int nf = 0; nf < 8; nf++) {
                const int jj  = nf & 3;
                const int sp_ = nf >> 2;
                const int kk0 = w * 16 + g;        // n0 & 63
                const int kk1 = kk0 + 8;           // n1 & 63
                const int lane0 = ((kk0 & 7) << 2) | l4;
                const int lane1 = ((kk1 & 7) << 2) | l4;
                const int idx0 = (((kk0 >> 3) * 2 + sp_) * 32 + lane0) * 4 + jj;
                const int idx1 = (((kk1 >> 3) * 2 + sp_) * 32 + lane1) * 4 + jj;
                img[idx0] = __floats2half2_rn(acc[nf][0], acc[nf][1]);
                img[idx1] = __floats2half2_rn(acc[nf][2], acc[nf][3]);
            }
        }
    }
}

// ============================================================================
// K transpose for rescan:  g_Kh[h][node][d] -> g_KhT[h][d][node]
// ============================================================================
__global__ __launch_bounds__(256) void transpose_k() {
    __shared__ float t[32][33];
    const int h  = blockIdx.z;
    const int d0 = blockIdx.y * 32;
    const int n0 = blockIdx.x * 32;
    const int txx = threadIdx.x, tyy = threadIdx.y;
    const float* src = g_Kh + (size_t)h * N_NODES * 64;
#pragma unroll
    for (int i = tyy; i < 32; i += 8)
        t[i][txx] = src[(size_t)(n0 + i) * 64 + d0 + txx];
    __syncthreads();
    float* dst = g_KhT + (size_t)h * 64 * N_NODES;
#pragma unroll
    for (int i = tyy; i < 32; i += 8)
        dst[(size_t)(d0 + i) * N_NODES + n0 + txx] = t[txx][i];
}

// ============================================================================
// rare index recovery (validated)
// ============================================================================
__device__ __forceinline__ void rare2(const float (&acc)[8][4], int cofs,
                                      int t, int l4, float tmax,
                                      float& best, float& best2, int& bk) {
    float sec = -3e38f;
    int   idx = bk;
    bool  taken = false;
#pragma unroll
    for (int nf = 0; nf < 8; nf++)
#pragma unroll
        for (int c = 0; c < 2; c++) {
            const float v = acc[nf][cofs + c];
            if (v == tmax && !taken) {
                taken = true;
                idx = t * 64 + nf * 8 + l4 * 2 + c;
            } else {
                sec = fmaxf(sec, v);
            }
        }
    best2 = fmaxf(best2, fmaxf(best, sec));
    best  = tmax;
    bk    = idx;
}

// ============================================================================
// Score argmax via mma.sync m16n8k16.f16; mask words prefetched 1 tile ahead.
// ============================================================================
__global__ __launch_bounds__(128, 4) void score_mma() {
    __shared__ __align__(16) __half sK[4][4096];
    __shared__ __align__(8) unsigned long long s_bar[4];

    const int tid  = threadIdx.x;
    const int w    = tid >> 5;
    const int lane = tid & 31;
    const int g    = lane >> 2;
    const int l4   = lane & 3;
    const int h    = blockIdx.y;
    const int qt   = blockIdx.x;
    const int qA   = qt * 64 + w * 16 + g;
    const int qB   = qA + 8;

    uint32_t bar[4];
#pragma unroll
    for (int i = 0; i < 4; i++) bar[i] = smem_u32(&s_bar[i]);
    const __half* Ksrc = g_Kp16 + (size_t)h * 64 * 4096;

    if (tid == 0) {
#pragma unroll
        for (int i = 0; i < 4; i++) mbar_init(bar[i], 1);
    }
    __syncthreads();

    if (tid == 0) {
#pragma unroll
        for (int i = 0; i < 4; i++) {
            mbar_arrive_expect(bar[i], 8192);
            bulk_g2s(smem_u32(&sK[i][0]), Ksrc + (size_t)i * 4096, 8192, bar[i]);
        }
    }

    uint32_t a[4][4];
    {
        const float* QA = g_Qh + ((size_t)h * N_NODES + qA) * 64;
        const float* QB = QA + 8 * 64;
#pragma unroll
        for (int s = 0; s < 4; s++) {
            const int c = s * 16 + 2 * l4;
            a[s][0] = pack_h2(QA[c],     QA[c + 1]);
            a[s][1] = pack_h2(QB[c],     QB[c + 1]);
            a[s][2] = pack_h2(QA[c + 8], QA[c + 9]);
            a[s][3] = pack_h2(QB[c + 8], QB[c + 9]);
        }
    }

    float bestA = -3.3e38f, best2A = -3.3e38f;
    float bestB = -3.3e38f, best2B = -3.3e38f;
    int   bkA = 0, bkB = 0;

    unsigned cw0A = g_adjbits[0 * N_NODES + qA];
    unsigned cw1A = g_adjbits[1 * N_NODES + qA];
    unsigned cw0B = g_adjbits[0 * N_NODES + qB];
    unsigned cw1B = g_adjbits[1 * N_NODES + qB];

    for (int t = 0; t < 64; t++) {
        const int buf = t & 3;
        const int ph  = (t >> 2) & 1;

        float acc[8][4];
#pragma unroll
        for (int nf = 0; nf < 8; nf++) {
            const unsigned wdA = (nf < 4) ? cw0A : cw1A;
            const unsigned wdB = (nf < 4) ? cw0B : cw1B;
            const int sh = (nf & 3) * 8 + l4 * 2;
            acc[nf][0] = ((wdA >> sh) & 1u)       ? 0.0f : -3e38f;
            acc[nf][1] = ((wdA >> (sh + 1)) & 1u) ? 0.0f : -3e38f;
            acc[nf][2] = ((wdB >> sh) & 1u)       ? 0.0f : -3e38f;
            acc[nf][3] = ((wdB >> (sh + 1)) & 1u) ? 0.0f : -3e38f;
        }
        if (t + 1 < 64) {
            cw0A = g_adjbits[(size_t)(2 * t + 2) * N_NODES + qA];
            cw1A = g_adjbits[(size_t)(2 * t + 3) * N_NODES + qA];
            cw0B = g_adjbits[(size_t)(2 * t + 2) * N_NODES + qB];
            cw1B = g_adjbits[(size_t)(2 * t + 3) * N_NODES + qB];
        }

        mbar_wait(bar[buf], ph);
        const __half* kb = &sK[buf][0];
#pragma unroll
        for (int nf = 0; nf < 8; nf++) {
#pragma unroll
            for (int sp = 0; sp < 2; sp++) {
                const uint4 bb = *(const uint4*)&kb[(size_t)(((nf * 2 + sp) * 32 + lane)) * 8];
                mma16(acc[nf], a[2 * sp],     bb.x, bb.y);
                mma16(acc[nf], a[2 * sp + 1], bb.z, bb.w);
            }
        }
        __syncthreads();
        if (tid == 0 && t + 4 < 64) {
            mbar_arrive_expect(bar[buf], 8192);
            bulk_g2s(smem_u32(&sK[buf][0]), Ksrc + (size_t)(t + 4) * 4096, 8192, bar[buf]);
        }

        float tA = fmaxf(acc[0][0], acc[0][1]);
        float tB = fmaxf(acc[0][2], acc[0][3]);
#pragma unroll
        for (int nf = 1; nf < 8; nf++) {
            tA = fmaxf(tA, fmaxf(acc[nf][0], acc[nf][1]));
            tB = fmaxf(tB, fmaxf(acc[nf][2], acc[nf][3]));
        }
        if (tA > bestA) rare2(acc, 0, t, l4, tA, bestA, best2A, bkA);
        else            best2A = fmaxf(best2A, tA);
        if (tB > bestB) rare2(acc, 2, t, l4, tB, bestB, best2B, bkB);
        else            best2B = fmaxf(best2B, tB);
    }

#pragma unroll
    for (int off = 1; off < 4; off <<= 1) {
        float ob  = __shfl_xor_sync(0xffffffffu, bestA, off);
        int   obk = __shfl_xor_sync(0xffffffffu, bkA,  off);
        float ob2 = __shfl_xor_sync(0xffffffffu, best2A, off);
        best2A = fmaxf(fmaxf(best2A, ob2), fminf(bestA, ob));
        if (ob > bestA || (ob == bestA && obk < bkA)) { bestA = ob; bkA = obk; }

        ob  = __shfl_xor_sync(0xffffffffu, bestB, off);
        obk = __shfl_xor_sync(0xffffffffu, bkB,  off);
        ob2 = __shfl_xor_sync(0xffffffffu, best2B, off);
        best2B = fmaxf(fmaxf(best2B, ob2), fminf(bestB, ob));
        if (ob > bestB || (ob == bestB && obk < bkB)) { bestB = ob; bkB = obk; }
    }

    if (l4 == 0) {
        const int hqA = h * N_NODES + qA;
        const int hqB = h * N_NODES + qB;
        g_argmax[hqA] = bkA;
        g_argmax[hqB] = bkB;
        if (bestA - best2A < BAND) g_fixlist[atomicAdd(&g_fixcount, 1)] = hqA;
        if (bestB - best2B < BAND) g_fixlist[atomicAdd(&g_fixcount, 1)] = hqB;
    }
}

// ============================================================================
// Pass 2: exact fp32 re-argmax of flagged rows — coalesced via K^T.
// ============================================================================
__global__ __launch_bounds__(512) void rescan() {
    __shared__ float sq[64];
    __shared__ float s_best[16];
    __shared__ int   s_bk[16];
    const int nfix = g_fixcount;
    const int tid = threadIdx.x, lane = tid & 31, wrp = tid >> 5;

    for (int i = blockIdx.x; i < nfix; i += gridDim.x) {
        const int hq = g_fixlist[i];
        const int h = hq >> 12, q = hq & (N_NODES - 1);
        if (tid < 64) sq[tid] = g_Qh[((size_t)h * N_NODES + q) * 64 + tid];
        __syncthreads();

        const float4* KT = (const float4*)(g_KhT + (size_t)h * 64 * N_NODES);
        float acc[8] = {0.f, 0.f, 0.f, 0.f, 0.f, 0.f, 0.f, 0.f};
#pragma unroll 4
        for (int d = 0; d < 64; d++) {
            const float qd = sq[d];
            const float4 v0 = KT[(size_t)d * 1024 + tid];
            const float4 v1 = KT[(size_t)d * 1024 + 512 + tid];
            acc[0] += qd * v0.x; acc[1] += qd * v0.y;
            acc[2] += qd * v0.z; acc[3] += qd * v0.w;
            acc[4] += qd * v1.x; acc[5] += qd * v1.y;
            acc[6] += qd * v1.z; acc[7] += qd * v1.w;
        }

        const int k0 = tid * 4, k1 = 2048 + tid * 4;
        const unsigned w0 = g_adjbits[(size_t)(k0 >> 5) * N_NODES + q];
        const unsigned w1 = g_adjbits[(size_t)(k1 >> 5) * N_NODES + q];
        float best = -3e38f;
        int   bk   = 1 << 30;
#pragma unroll
        for (int j = 0; j < 4; j++) {
            if ((w0 >> ((k0 + j) & 31)) & 1u)
                if (acc[j] > best) { best = acc[j]; bk = k0 + j; }
        }
#pragma unroll
        for (int j = 0; j < 4; j++) {
            if ((w1 >> ((k1 + j) & 31)) & 1u)
                if (acc[4 + j] > best) { best = acc[4 + j]; bk = k1 + j; }
        }
#pragma unroll
        for (int off = 16; off > 0; off >>= 1) {
            float ob  = __shfl_xor_sync(0xffffffffu, best, off);
            int   obk = __shfl_xor_sync(0xffffffffu, bk, off);
            if (ob > best || (ob == best && obk < bk)) { best = ob; bk = obk; }
        }
        if (lane == 0) { s_best[wrp] = best; s_bk[wrp] = bk; }
        __syncthreads();
        if (tid == 0) {
            float b = s_best[0]; int k = s_bk[0];
#pragma unroll
            for (int j = 1; j < 16; j++)
                if (s_best[j] > b || (s_best[j] == b && s_bk[j] < k)) {
                    b = s_best[j]; k = s_bk[j];
                }
            g_argmax[hq] = k;
        }
        __syncthreads();
    }
}

// ============================================================================
// out[q, h*64+d] = V[argmax(h,q), h*64+d] / HEADS
// ============================================================================
__global__ __launch_bounds__(256) void gather_out(float* __restrict__ out) {
    const int idx = blockIdx.x * blockDim.x + threadIdx.x;
    const int q   = idx >> 7;
    const int c4  = idx & 127;
    const int h   = c4 >> 4;
    const int k   = g_argmax[h * N_NODES + q];
    float4 t = *(const float4*)&g_V[(size_t)k * 512 + c4 * 4];
    float4 v = make_float4(t.x * 0.125f, t.y * 0.125f, t.z * 0.125f, t.w * 0.125f);
    *(float4*)&out[(size_t)idx * 4] = v;
}

// ============================================================================
extern "C" void kernel_launch(void* const* d_in, const int* in_sizes, int n_in,
                              void* d_out, int out_size)
{
    const float* x   = (const float*)d_in[0];
    const int*   adj = (const int*)d_in[1];
    const float* WQ  = (const float*)d_in[2];
    const float* WK  = (const float*)d_in[3];
    const float* WV  = (const float*)d_in[4];
    float* out = (float*)d_out;

    cudaFuncSetAttribute(proj_mma,
                         cudaFuncAttributeMaxDynamicSharedMemorySize, VM_SMEM);

    prep_all<<<1216, 256>>>(x, WQ, WK, WV, adj);

    proj_mma<<<dim3(64, 24), 128, VM_SMEM>>>();

    dim3 tb(32, 8);
    transpose_k<<<dim3(N_NODES / 32, 2, HEADS), tb>>>();

    score_mma<<<dim3(N_NODES / 64, HEADS), 128>>>();

    rescan<<<512, 512>>>();

    gather_out<<<(N_NODES * 512 / 4) / 256, 256>>>(out);
}